// round 11
// baseline (speedup 1.0000x reference)
#include <cuda_runtime.h>
#include <cuda_bf16.h>
#include <cuda_fp16.h>
#include <cstdint>

#define B_SZ 512
#define H_SZ 1024
#define L_SZ 64
#define V_SZ 50257
#define LDL  50304   // padded logits / W row stride (128*393)
#define NB_T 393     // 128-wide n-tiles in vocab GEMM

// ---------------- scratch (device globals; no allocation allowed) ----------
__device__ float g_xin[B_SZ * 2 * H_SZ];
__device__ float g_x[B_SZ * H_SZ];
__device__ float g_gi[B_SZ * 3 * H_SZ];
__device__ float g_gh[B_SZ * 3 * H_SZ];
__device__ __nv_bfloat16 g_h1b[B_SZ * H_SZ];
__device__ __nv_bfloat16 g_wbf[(size_t)H_SZ * LDL];   // bf16 W k-major, padded
__device__ __half g_logith[(size_t)B_SZ * LDL];       // fp16 logits, 51MB
__device__ float2 g_part[B_SZ * 400];

// ---------------- helpers ----------------
__device__ __forceinline__ void cp_async16_cg(uint32_t dst, const void* src) {
    asm volatile("cp.async.cg.shared.global [%0], [%1], 16;" :: "r"(dst), "l"(src));
}
__device__ __forceinline__ void cp_async16_ca(uint32_t dst, const void* src) {
    asm volatile("cp.async.ca.shared.global [%0], [%1], 16;" :: "r"(dst), "l"(src));
}
__device__ __forceinline__ void cp_commit() {
    asm volatile("cp.async.commit_group;");
}
template <int N>
__device__ __forceinline__ void cp_wait() {
    asm volatile("cp.async.wait_group %0;" :: "n"(N));
}
__device__ __forceinline__ uint32_t smem_u32(const void* p) {
    return (uint32_t)__cvta_generic_to_shared(p);
}
#define LDMX4(R0,R1,R2,R3,ADDR) \
    asm volatile("ldmatrix.sync.aligned.m8n8.x4.shared.b16 {%0,%1,%2,%3}, [%4];" \
        : "=r"(R0), "=r"(R1), "=r"(R2), "=r"(R3) : "r"(ADDR))
#define LDMX4T(R0,R1,R2,R3,ADDR) \
    asm volatile("ldmatrix.sync.aligned.m8n8.x4.trans.shared.b16 {%0,%1,%2,%3}, [%4];" \
        : "=r"(R0), "=r"(R1), "=r"(R2), "=r"(R3) : "r"(ADDR))

__device__ __forceinline__ float safe_scale(float s, float m, float mn) {
    return (m > -1e37f) ? s * expf(m - mn) : 0.f;
}

// ===========================================================================
// K0: convert out_W fp32 (1024 x 50257) -> bf16 padded k-major (1024 x LDL)
// ===========================================================================
__global__ void __launch_bounds__(256) convw_kernel(const float* __restrict__ W)
{
    size_t id = (size_t)blockIdx.x * 256 + threadIdx.x;
    int k  = (int)(id / (LDL / 8));
    int n8 = (int)(id % (LDL / 8)) * 8;
    const float* wr = W + (size_t)k * V_SZ;
    float f[8];
    if (n8 + 7 < V_SZ) {
        #pragma unroll
        for (int j = 0; j < 8; j++) f[j] = wr[n8 + j];
    } else {
        #pragma unroll
        for (int j = 0; j < 8; j++) f[j] = (n8 + j < V_SZ) ? wr[n8 + j] : 0.f;
    }
    __nv_bfloat162 p0 = __floats2bfloat162_rn(f[0], f[1]);
    __nv_bfloat162 p1 = __floats2bfloat162_rn(f[2], f[3]);
    __nv_bfloat162 p2 = __floats2bfloat162_rn(f[4], f[5]);
    __nv_bfloat162 p3 = __floats2bfloat162_rn(f[6], f[7]);
    uint4 v; v.x = *(unsigned*)&p0; v.y = *(unsigned*)&p1;
    v.z = *(unsigned*)&p2; v.w = *(unsigned*)&p3;
    *(uint4*)&g_wbf[(size_t)k * LDL + n8] = v;
}

// ===========================================================================
// K1: attention + concat input (R4-exact)
// ===========================================================================
__global__ void __launch_bounds__(256) attn_kernel(
    const float* __restrict__ emb, const float* __restrict__ h0,
    const float* __restrict__ enc, const float* __restrict__ attn_W,
    const float* __restrict__ attn_b, float* __restrict__ aw_out)
{
    __shared__ float sE[4][H_SZ];
    __shared__ float sH[4][H_SZ];
    __shared__ float sS[4][L_SZ];
    __shared__ float sP[4][4][L_SZ];

    int tid = threadIdx.x;
    int r0  = blockIdx.x * 4;

    for (int i = tid; i < 4 * H_SZ; i += 256) {
        int r = i >> 10, c = i & 1023;
        sE[r][c] = emb[(size_t)(r0 + r) * H_SZ + c];
        sH[r][c] = h0 [(size_t)(r0 + r) * H_SZ + c];
    }
    __syncthreads();

    {
        int l = tid & 63, gq = tid >> 6;
        float acc[4] = {0.f, 0.f, 0.f, 0.f};
        int kbeg = gq * 512, kend = kbeg + 512;
        for (int k = kbeg; k < kend; k++) {
            float w = attn_W[(size_t)k * L_SZ + l];
            if (k < H_SZ) {
                #pragma unroll
                for (int r = 0; r < 4; r++) acc[r] += sE[r][k] * w;
            } else {
                #pragma unroll
                for (int r = 0; r < 4; r++) acc[r] += sH[r][k - H_SZ] * w;
            }
        }
        #pragma unroll
        for (int r = 0; r < 4; r++) sP[gq][r][l] = acc[r];
    }
    __syncthreads();
    {
        int r = tid >> 6, l = tid & 63;
        sS[r][l] = sP[0][r][l] + sP[1][r][l] + sP[2][r][l] + sP[3][r][l] + attn_b[l];
    }
    __syncthreads();

    int warp = tid >> 5, lane = tid & 31;
    if (warp < 4) {
        int r = warp;
        float v0 = sS[r][lane], v1 = sS[r][lane + 32];
        float m = fmaxf(v0, v1);
        #pragma unroll
        for (int o = 16; o; o >>= 1) m = fmaxf(m, __shfl_xor_sync(0xffffffffu, m, o));
        float e0 = expf(v0 - m), e1 = expf(v1 - m);
        float s = e0 + e1;
        #pragma unroll
        for (int o = 16; o; o >>= 1) s += __shfl_xor_sync(0xffffffffu, s, o);
        float inv = 1.0f / s;
        float w0 = e0 * inv, w1 = e1 * inv;
        sS[r][lane] = w0; sS[r][lane + 32] = w1;
        if (aw_out) {
            aw_out[(size_t)(r0 + r) * L_SZ + lane]      = w0;
            aw_out[(size_t)(r0 + r) * L_SZ + lane + 32] = w1;
        }
    }
    __syncthreads();

    for (int cc = 0; cc < 4; cc++) {
        int h = cc * 256 + tid;
        float a[4] = {0.f, 0.f, 0.f, 0.f};
        for (int l = 0; l < L_SZ; l++) {
            float e = enc[(size_t)l * H_SZ + h];
            #pragma unroll
            for (int r = 0; r < 4; r++) a[r] += sS[r][l] * e;
        }
        #pragma unroll
        for (int r = 0; r < 4; r++) {
            g_xin[(size_t)(r0 + r) * (2 * H_SZ) + h]        = sE[r][h];
            g_xin[(size_t)(r0 + r) * (2 * H_SZ) + H_SZ + h] = a[r];
        }
    }
}

// ===========================================================================
// tf32 mma GEMM core (R4-exact: kstep 16, 2-stage cp.async)
// ===========================================================================
__device__ __forceinline__ void gemm_tf32_core(
    float (*sA)[64][20], float (*sB)[64][20],
    const float* __restrict__ A, const float* __restrict__ Bm,
    const float* __restrict__ bias, float* __restrict__ C,
    int N, int K, int b_kmajor, int relu, int bm0, int bn0)
{
    int tid = threadIdx.x;
    int warp = tid >> 5, lane = tid & 31, g = lane >> 2, q = lane & 3;
    int wm = warp & 1, wn = warp >> 1;

    int lr = tid >> 2, lc4 = (tid & 3) * 4;
    int tkr = tid >> 4, tc4 = (tid & 15) * 4;

    float acc[2][2][4];
    #pragma unroll
    for (int i = 0; i < 2; i++)
        #pragma unroll
        for (int j = 0; j < 2; j++)
            #pragma unroll
            for (int t = 0; t < 4; t++) acc[i][j][t] = 0.f;

    const int NS = K / 16;
    {
        cp_async16_ca(smem_u32(&sA[0][lr][lc4]), A + (size_t)(bm0 + lr) * K + lc4);
        if (b_kmajor) {
            cp_async16_cg(smem_u32(&sB[0][lr][lc4]), Bm + (size_t)(bn0 + lr) * K + lc4);
        } else {
            float4 v = *(const float4*)(Bm + (size_t)tkr * N + bn0 + tc4);
            sB[0][tc4][tkr] = v.x; sB[0][tc4 + 1][tkr] = v.y;
            sB[0][tc4 + 2][tkr] = v.z; sB[0][tc4 + 3][tkr] = v.w;
        }
        cp_commit();
    }

    for (int ks = 0; ks < NS; ks++) {
        int buf = ks & 1;
        bool hasNext = (ks + 1) < NS;
        cp_wait<0>();
        __syncthreads();
        float4 vB;
        if (hasNext) {
            int k0 = (ks + 1) * 16;
            int nb = buf ^ 1;
            cp_async16_ca(smem_u32(&sA[nb][lr][lc4]),
                          A + (size_t)(bm0 + lr) * K + k0 + lc4);
            if (b_kmajor)
                cp_async16_cg(smem_u32(&sB[nb][lr][lc4]),
                              Bm + (size_t)(bn0 + lr) * K + k0 + lc4);
            else
                vB = *(const float4*)(Bm + (size_t)(k0 + tkr) * N + bn0 + tc4);
            cp_commit();
        }

        #pragma unroll
        for (int kk = 0; kk < 2; kk++) {
            int ko = kk * 8;
            unsigned a[2][4], b[2][2];
            #pragma unroll
            for (int mt = 0; mt < 2; mt++) {
                int rm = wm * 32 + mt * 16;
                a[mt][0] = __float_as_uint(sA[buf][rm + g][ko + q]);
                a[mt][1] = __float_as_uint(sA[buf][rm + g + 8][ko + q]);
                a[mt][2] = __float_as_uint(sA[buf][rm + g][ko + q + 4]);
                a[mt][3] = __float_as_uint(sA[buf][rm + g + 8][ko + q + 4]);
            }
            #pragma unroll
            for (int nt = 0; nt < 2; nt++) {
                int cn = wn * 16 + nt * 8 + g;
                b[nt][0] = __float_as_uint(sB[buf][cn][ko + q]);
                b[nt][1] = __float_as_uint(sB[buf][cn][ko + q + 4]);
            }
            #pragma unroll
            for (int mt = 0; mt < 2; mt++)
                #pragma unroll
                for (int nt = 0; nt < 2; nt++)
                    asm volatile(
                        "mma.sync.aligned.m16n8k8.row.col.f32.tf32.tf32.f32 "
                        "{%0,%1,%2,%3}, {%4,%5,%6,%7}, {%8,%9}, {%0,%1,%2,%3};"
                        : "+f"(acc[mt][nt][0]), "+f"(acc[mt][nt][1]),
                          "+f"(acc[mt][nt][2]), "+f"(acc[mt][nt][3])
                        : "r"(a[mt][0]), "r"(a[mt][1]), "r"(a[mt][2]), "r"(a[mt][3]),
                          "r"(b[nt][0]), "r"(b[nt][1]));
        }

        if (hasNext && !b_kmajor) {
            int nb = buf ^ 1;
            sB[nb][tc4][tkr] = vB.x; sB[nb][tc4 + 1][tkr] = vB.y;
            sB[nb][tc4 + 2][tkr] = vB.z; sB[nb][tc4 + 3][tkr] = vB.w;
        }
    }

    #pragma unroll
    for (int mt = 0; mt < 2; mt++) {
        int row = bm0 + wm * 32 + mt * 16 + g;
        #pragma unroll
        for (int nt = 0; nt < 2; nt++) {
            int col = bn0 + wn * 16 + nt * 8 + 2 * q;
            float b0 = bias[col], b1 = bias[col + 1];
            float v0 = acc[mt][nt][0] + b0, v1 = acc[mt][nt][1] + b1;
            float v2 = acc[mt][nt][2] + b0, v3 = acc[mt][nt][3] + b1;
            if (relu) {
                v0 = fmaxf(v0, 0.f); v1 = fmaxf(v1, 0.f);
                v2 = fmaxf(v2, 0.f); v3 = fmaxf(v3, 0.f);
            }
            C[(size_t)row * N + col] = v0;       C[(size_t)row * N + col + 1] = v1;
            C[(size_t)(row + 8) * N + col] = v2; C[(size_t)(row + 8) * N + col + 1] = v3;
        }
    }
}

__global__ void __launch_bounds__(256) comb_ghh_kernel(
    const float* __restrict__ comb_W, const float* __restrict__ comb_b,
    const float* __restrict__ h0, const float* __restrict__ W_hh,
    const float* __restrict__ b_hh)
{
    __shared__ float sA[2][64][20];
    __shared__ float sB[2][64][20];
    if (blockIdx.z == 0) {
        gemm_tf32_core(sA, sB, g_xin, comb_W, comb_b, g_x,
                       H_SZ, 2 * H_SZ, 0, 1, blockIdx.x * 64, blockIdx.y * 64);
    } else {
        int bn = (blockIdx.z - 1) * 16 + blockIdx.y;
        gemm_tf32_core(sA, sB, h0, W_hh, b_hh, g_gh,
                       3 * H_SZ, H_SZ, 1, 0, blockIdx.x * 64, bn * 64);
    }
}
__global__ void __launch_bounds__(256) gemm_gih_kernel(
    const float* __restrict__ W_ih, const float* __restrict__ b_ih)
{
    __shared__ float sA[2][64][20];
    __shared__ float sB[2][64][20];
    gemm_tf32_core(sA, sB, g_x, W_ih, b_ih, g_gi,
                   3 * H_SZ, H_SZ, 1, 0, blockIdx.x * 64, blockIdx.y * 64);
}

// ===========================================================================
// K4: GRU elementwise (R4-exact)
// ===========================================================================
__global__ void __launch_bounds__(256) gru_kernel(
    const float* __restrict__ h0, float* __restrict__ h1_extra)
{
    int idx = blockIdx.x * 256 + threadIdx.x;
    if (idx >= B_SZ * H_SZ) return;
    int row = idx >> 10, j = idx & 1023;
    const float* gi = g_gi + (size_t)row * 3 * H_SZ;
    const float* gh = g_gh + (size_t)row * 3 * H_SZ;
    float rg = 1.f / (1.f + expf(-(gi[j] + gh[j])));
    float zg = 1.f / (1.f + expf(-(gi[H_SZ + j] + gh[H_SZ + j])));
    float ng = tanhf(gi[2 * H_SZ + j] + rg * gh[2 * H_SZ + j]);
    float h0v = h0[idx];
    float h1 = (1.f - zg) * ng + zg * h0v;
    g_h1b[idx] = __float2bfloat16(h1);
    if (h1_extra) h1_extra[idx] = h1;
}

// ===========================================================================
// K5: vocab GEMM (R10-measured 201us: 128x128x32, 5-stage cp.async, 2 CTA/SM),
//   fp16 logits + per-(row,n-tile) (max,sumexp) partials.
// ===========================================================================
#define OUT_STAGES 5
#define A_STAGE_B  8192
#define B_STAGE_B  8192

__global__ void __launch_bounds__(256, 2) gemm_out_kernel(
    const float* __restrict__ bias)
{
    extern __shared__ __nv_bfloat16 dynsmem[];
    __shared__ float2 spart[128][4];

    const int K = 1024;
    int tid = threadIdx.x;
    int warp = tid >> 5, lane = tid & 31, g = lane >> 2, q = lane & 3;
    int wm = warp & 1, wn = warp >> 1;
    int bm0 = blockIdx.x * 128, bn0 = blockIdx.y * 128;

    uint32_t smem_b = smem_u32(dynsmem);
    uint32_t sB_b   = smem_b + OUT_STAGES * A_STAGE_B;

    int a_r0 = tid >> 2,  a_c0 = tid & 3;
    int b_k0 = tid >> 4,  b_c0 = tid & 15;
    uint32_t a_dst0 = a_r0 * 64 + ((a_c0 ^ ((a_r0 >> 1) & 3)) << 4);
    uint32_t a_dst1 = (a_r0 + 64) * 64 + ((a_c0 ^ (((a_r0 + 64) >> 1) & 3)) << 4);
    uint32_t b_dst0 = b_k0 * 256 + ((b_c0 ^ (b_k0 & 7)) << 4);
    uint32_t b_dst1 = (b_k0 + 16) * 256 + ((b_c0 ^ ((b_k0 + 16) & 7)) << 4);
    const __nv_bfloat16* a_src0 = g_h1b + (size_t)(bm0 + a_r0) * K + a_c0 * 8;
    const __nv_bfloat16* a_src1 = g_h1b + (size_t)(bm0 + a_r0 + 64) * K + a_c0 * 8;
    const __nv_bfloat16* b_src0 = g_wbf + (size_t)b_k0 * LDL + bn0 + b_c0 * 8;
    const __nv_bfloat16* b_src1 = g_wbf + (size_t)(b_k0 + 16) * LDL + bn0 + b_c0 * 8;

    int a_row[4];
    #pragma unroll
    for (int mt = 0; mt < 4; mt++) a_row[mt] = wm * 64 + mt * 16 + (lane & 15);
    int b_lk = lane & 15, b_lc = lane >> 4;

    float acc[4][4][4];
    #pragma unroll
    for (int i = 0; i < 4; i++)
        #pragma unroll
        for (int j = 0; j < 4; j++)
            #pragma unroll
            for (int t = 0; t < 4; t++) acc[i][j][t] = 0.f;

    #pragma unroll
    for (int st = 0; st < OUT_STAGES - 1; st++) {
        uint32_t ab = smem_b + st * A_STAGE_B;
        uint32_t bb = sB_b   + st * B_STAGE_B;
        int k0 = st * 32;
        cp_async16_ca(ab + a_dst0, a_src0 + k0);
        cp_async16_ca(ab + a_dst1, a_src1 + k0);
        cp_async16_cg(bb + b_dst0, b_src0 + (size_t)k0 * LDL);
        cp_async16_cg(bb + b_dst1, b_src1 + (size_t)k0 * LDL);
        cp_commit();
    }

    int slot = 0;
    for (int ks = 0; ks < 32; ks++) {
        cp_wait<OUT_STAGES - 2>();
        __syncthreads();

        uint32_t ab = smem_b + slot * A_STAGE_B;
        uint32_t bb = sB_b   + slot * B_STAGE_B;
        #pragma unroll
        for (int kk = 0; kk < 2; kk++) {
            unsigned a[4][4], b[4][2];
            #pragma unroll
            for (int mt = 0; mt < 4; mt++) {
                int chunk = kk * 2 + (lane >> 4);
                uint32_t addr = ab + a_row[mt] * 64 +
                                ((chunk ^ ((a_row[mt] >> 1) & 3)) << 4);
                LDMX4(a[mt][0], a[mt][1], a[mt][2], a[mt][3], addr);
            }
            #pragma unroll
            for (int h = 0; h < 2; h++) {
                int krow = kk * 16 + b_lk;
                int c = wn * 4 + 2 * h + b_lc;
                uint32_t addr = bb + krow * 256 + ((c ^ (krow & 7)) << 4);
                unsigned r0, r1, r2, r3;
                LDMX4T(r0, r1, r2, r3, addr);
                b[2 * h][0] = r0;     b[2 * h][1] = r1;
                b[2 * h + 1][0] = r2; b[2 * h + 1][1] = r3;
            }
            #pragma unroll
            for (int mt = 0; mt < 4; mt++)
                #pragma unroll
                for (int nt = 0; nt < 4; nt++)
                    asm volatile(
                        "mma.sync.aligned.m16n8k16.row.col.f32.bf16.bf16.f32 "
                        "{%0,%1,%2,%3}, {%4,%5,%6,%7}, {%8,%9}, {%0,%1,%2,%3};"
                        : "+f"(acc[mt][nt][0]), "+f"(acc[mt][nt][1]),
                          "+f"(acc[mt][nt][2]), "+f"(acc[mt][nt][3])
                        : "r"(a[mt][0]), "r"(a[mt][1]), "r"(a[mt][2]), "r"(a[mt][3]),
                          "r"(b[nt][0]), "r"(b[nt][1]));
        }

        int nst = ks + OUT_STAGES - 1;
        if (nst < 32) {
            int wslot = nst % OUT_STAGES;
            uint32_t ab2 = smem_b + wslot * A_STAGE_B;
            uint32_t bb2 = sB_b   + wslot * B_STAGE_B;
            int k0 = nst * 32;
            cp_async16_ca(ab2 + a_dst0, a_src0 + k0);
            cp_async16_ca(ab2 + a_dst1, a_src1 + k0);
            cp_async16_cg(bb2 + b_dst0, b_src0 + (size_t)k0 * LDL);
            cp_async16_cg(bb2 + b_dst1, b_src1 + (size_t)k0 * LDL);
            cp_commit();
        }
        slot = (slot + 1 == OUT_STAGES) ? 0 : slot + 1;
    }

    // ---- epilogue: bias, fp16 logits, (max,sumexp) partials ----
    #pragma unroll
    for (int mt = 0; mt < 4; mt++) {
        int row = bm0 + wm * 64 + mt * 16 + g;
        #pragma unroll
        for (int nt = 0; nt < 4; nt++) {
            int col = bn0 + wn * 32 + nt * 8 + 2 * q;
            float b0 = (col < V_SZ)     ? bias[col]     : 0.f;
            float b1 = (col + 1 < V_SZ) ? bias[col + 1] : 0.f;
            acc[mt][nt][0] = (col < V_SZ)     ? acc[mt][nt][0] + b0 : -1e38f;
            acc[mt][nt][1] = (col + 1 < V_SZ) ? acc[mt][nt][1] + b1 : -1e38f;
            acc[mt][nt][2] = (col < V_SZ)     ? acc[mt][nt][2] + b0 : -1e38f;
            acc[mt][nt][3] = (col + 1 < V_SZ) ? acc[mt][nt][3] + b1 : -1e38f;
            *(__half2*)(g_logith + (size_t)row * LDL + col) =
                __floats2half2_rn(acc[mt][nt][0], acc[mt][nt][1]);
            *(__half2*)(g_logith + (size_t)(row + 8) * LDL + col) =
                __floats2half2_rn(acc[mt][nt][2], acc[mt][nt][3]);
        }
    }

    #pragma unroll
    for (int mt = 0; mt < 4; mt++) {
        #pragma unroll
        for (int half = 0; half < 2; half++) {
            int lr = wm * 64 + mt * 16 + g + 8 * half;
            float mx = -1e38f, sm = 0.f;
            #pragma unroll
            for (int nt = 0; nt < 4; nt++)
                mx = fmaxf(mx, fmaxf(acc[mt][nt][2 * half], acc[mt][nt][2 * half + 1]));
            #pragma unroll
            for (int nt = 0; nt < 4; nt++) {
                float v0 = acc[mt][nt][2 * half], v1 = acc[mt][nt][2 * half + 1];
                if (v0 > -1e37f) sm += expf(v0 - mx);
                if (v1 > -1e37f) sm += expf(v1 - mx);
            }
            #pragma unroll
            for (int o = 1; o <= 2; o <<= 1) {
                float mo = __shfl_xor_sync(0xffffffffu, mx, o);
                float so = __shfl_xor_sync(0xffffffffu, sm, o);
                float mn = fmaxf(mx, mo);
                sm = safe_scale(sm, mx, mn) + safe_scale(so, mo, mn);
                mx = mn;
            }
            if (q == 0) spart[lr][wn] = make_float2(mx, sm);
        }
    }
    __syncthreads();
    if (tid < 128) {
        float mx = -1e38f, sm = 0.f;
        #pragma unroll
        for (int w = 0; w < 4; w++) {
            float2 p = spart[tid][w];
            float mn = fmaxf(mx, p.x);
            sm = safe_scale(sm, mx, mn) + safe_scale(p.y, p.x, mn);
            mx = mn;
        }
        g_part[(size_t)(bm0 + tid) * 400 + blockIdx.y] = make_float2(mx, sm);
    }
}

// ===========================================================================
// K6: log_softmax from partials; 2 blocks per row (half-row each).
// ===========================================================================
__global__ void __launch_bounds__(256) lsm_kernel(float* __restrict__ outp)
{
    __shared__ float sredm[8];
    __shared__ float sreds[8];
    int row = blockIdx.x >> 1, halfb = blockIdx.x & 1;
    int tid = threadIdx.x, lane = tid & 31, warp = tid >> 5;

    float m = -1e38f, s = 0.f;
    for (int i = tid; i < NB_T; i += 256) {
        float2 p = g_part[(size_t)row * 400 + i];
        float mn = fmaxf(m, p.x);
        s = safe_scale(s, m, mn) + safe_scale(p.y, p.x, mn);
        m = mn;
    }
    #pragma unroll
    for (int o = 16; o; o >>= 1) {
        float mo = __shfl_xor_sync(0xffffffffu, m, o);
        float so = __shfl_xor_sync(0xffffffffu, s, o);
        float mn = fmaxf(m, mo);
        s = safe_scale(s, m, mn) + safe_scale(so, mo, mn);
        m = mn;
    }
    if (lane == 0) { sredm[warp] = m; sreds[warp] = s; }
    __syncthreads();
    float mall = sredm[0];
    #pragma unroll
    for (int i = 1; i < 8; i++) mall = fmaxf(mall, sredm[i]);
    float tot = 0.f;
    #pragma unroll
    for (int i = 0; i < 8; i++) tot += safe_scale(sreds[i], sredm[i], mall);
    float lse = mall + logf(tot);

    const __half* lg = g_logith + (size_t)row * LDL;
    float* op = outp + (size_t)row * V_SZ;
    // half 0: [0, 25128); half 1: [25128, V_SZ). 25128 % 8 == 0.
    const int HALF = 25128;
    int vbeg = halfb ? HALF : 0;
    int vend = halfb ? V_SZ : HALF;
    for (int v = vbeg + tid * 8; v + 7 < vend; v += 2048) {
        uint4 raw = *(const uint4*)(lg + v);
        float2 f0 = __half22float2(*(__half2*)&raw.x);
        float2 f1 = __half22float2(*(__half2*)&raw.y);
        float2 f2 = __half22float2(*(__half2*)&raw.z);
        float2 f3 = __half22float2(*(__half2*)&raw.w);
        op[v]     = f0.x - lse; op[v + 1] = f0.y - lse;
        op[v + 2] = f1.x - lse; op[v + 3] = f1.y - lse;
        op[v + 4] = f2.x - lse; op[v + 5] = f2.y - lse;
        op[v + 6] = f3.x - lse; op[v + 7] = f3.y - lse;
    }
    if (halfb && tid < 8) {
        int v = 50248 + tid;                // tail 50248..50256 (9 elems, 8 threads + 1)
        if (v < V_SZ) op[v] = __half2float(lg[v]) - lse;
        if (tid == 0) op[V_SZ - 1] = __half2float(lg[V_SZ - 1]) - lse;
    }
}

// ===========================================================================
// host launcher — R4 ordering
// ===========================================================================
extern "C" void kernel_launch(void* const* d_in, const int* in_sizes, int n_in,
                              void* d_out, int out_size)
{
    const float* input_emb = (const float*)d_in[0];
    const float* hidden    = (const float*)d_in[1];
    const float* enc       = (const float*)d_in[2];
    const float* attn_W    = (const float*)d_in[3];
    const float* attn_b    = (const float*)d_in[4];
    const float* comb_W    = (const float*)d_in[5];
    const float* comb_b    = (const float*)d_in[6];
    const float* W_ih      = (const float*)d_in[7];
    const float* W_hh      = (const float*)d_in[8];
    const float* b_ih      = (const float*)d_in[9];
    const float* b_hh      = (const float*)d_in[10];
    const float* out_W     = (const float*)d_in[11];
    const float* out_b     = (const float*)d_in[12];

    float* outp = (float*)d_out;
    long long osz = (long long)out_size;
    const long long OV = (long long)B_SZ * V_SZ;
    float* h1_out = (osz >= OV + (long long)B_SZ * H_SZ)
                        ? outp + (size_t)OV : nullptr;
    float* aw_out = (osz >= OV + (long long)B_SZ * H_SZ + (long long)B_SZ * L_SZ)
                        ? outp + (size_t)OV + (size_t)B_SZ * H_SZ : nullptr;

    const int OUT_SMEM = OUT_STAGES * (A_STAGE_B + B_STAGE_B);   // 80KB
    cudaFuncSetAttribute(gemm_out_kernel,
                         cudaFuncAttributeMaxDynamicSharedMemorySize, OUT_SMEM);

    // K0: W -> bf16 padded (serial first; saturates DRAM alone)
    convw_kernel<<<(H_SZ * (LDL / 8)) / 256, 256>>>(out_W);
    // K1: attention + concat
    attn_kernel<<<B_SZ / 4, 256>>>(input_emb, hidden, enc, attn_W, attn_b, aw_out);
    // K2: comb + ghh
    {
        dim3 grid(B_SZ / 64, 16, 4);
        comb_ghh_kernel<<<grid, 256>>>(comb_W, comb_b, hidden, W_hh, b_hh);
    }
    // K3: gih
    {
        dim3 grid(B_SZ / 64, 3 * H_SZ / 64);
        gemm_gih_kernel<<<grid, 256>>>(W_ih, b_ih);
    }
    // K4: GRU
    gru_kernel<<<(B_SZ * H_SZ) / 256, 256>>>(hidden, h1_out);
    // K5: vocab GEMM
    {
        dim3 grid(B_SZ / 128, NB_T);   // m fastest -> L2 reuse of W tiles
        gemm_out_kernel<<<grid, 256, OUT_SMEM>>>(out_b);
    }
    // K6: log_softmax (2 blocks/row)
    lsm_kernel<<<2 * B_SZ, 256>>>(outp);
}

// round 12
// speedup vs baseline: 1.0073x; 1.0073x over previous
#include <cuda_runtime.h>
#include <cuda_bf16.h>
#include <cuda_fp16.h>
#include <cstdint>

#define B_SZ 512
#define H_SZ 1024
#define L_SZ 64
#define V_SZ 50257
#define LDL  50304   // padded logits / W row stride (128*393)
#define NB_T 393     // 128-wide n-tiles in vocab GEMM

// ---------------- scratch (device globals; no allocation allowed) ----------
__device__ float g_xin[B_SZ * 2 * H_SZ];
__device__ float g_x[B_SZ * H_SZ];
__device__ float g_gi0[B_SZ * 3 * H_SZ];
__device__ float g_gi1[B_SZ * 3 * H_SZ];
__device__ float g_gh0[B_SZ * 3 * H_SZ];
__device__ float g_gh1[B_SZ * 3 * H_SZ];
__device__ __nv_bfloat16 g_h1b[B_SZ * H_SZ];
__device__ __nv_bfloat16 g_wbf[(size_t)H_SZ * LDL];   // bf16 W k-major, padded
__device__ __half g_logith[(size_t)B_SZ * LDL];       // fp16 logits, 51MB
__device__ float2 g_part[B_SZ * 400];

// ---------------- helpers ----------------
__device__ __forceinline__ void cp_async16_cg(uint32_t dst, const void* src) {
    asm volatile("cp.async.cg.shared.global [%0], [%1], 16;" :: "r"(dst), "l"(src));
}
__device__ __forceinline__ void cp_async16_ca(uint32_t dst, const void* src) {
    asm volatile("cp.async.ca.shared.global [%0], [%1], 16;" :: "r"(dst), "l"(src));
}
__device__ __forceinline__ void cp_commit() {
    asm volatile("cp.async.commit_group;");
}
template <int N>
__device__ __forceinline__ void cp_wait() {
    asm volatile("cp.async.wait_group %0;" :: "n"(N));
}
__device__ __forceinline__ uint32_t smem_u32(const void* p) {
    return (uint32_t)__cvta_generic_to_shared(p);
}
#define LDMX4(R0,R1,R2,R3,ADDR) \
    asm volatile("ldmatrix.sync.aligned.m8n8.x4.shared.b16 {%0,%1,%2,%3}, [%4];" \
        : "=r"(R0), "=r"(R1), "=r"(R2), "=r"(R3) : "r"(ADDR))
#define LDMX4T(R0,R1,R2,R3,ADDR) \
    asm volatile("ldmatrix.sync.aligned.m8n8.x4.trans.shared.b16 {%0,%1,%2,%3}, [%4];" \
        : "=r"(R0), "=r"(R1), "=r"(R2), "=r"(R3) : "r"(ADDR))

__device__ __forceinline__ float safe_scale(float s, float m, float mn) {
    return (m > -1e37f) ? s * expf(m - mn) : 0.f;
}

// ===========================================================================
// K0: convert out_W fp32 (1024 x 50257) -> bf16 padded k-major (1024 x LDL)
// ===========================================================================
__global__ void __launch_bounds__(256) convw_kernel(const float* __restrict__ W)
{
    size_t id = (size_t)blockIdx.x * 256 + threadIdx.x;
    int k  = (int)(id / (LDL / 8));
    int n8 = (int)(id % (LDL / 8)) * 8;
    const float* wr = W + (size_t)k * V_SZ;
    float f[8];
    if (n8 + 7 < V_SZ) {
        #pragma unroll
        for (int j = 0; j < 8; j++) f[j] = wr[n8 + j];
    } else {
        #pragma unroll
        for (int j = 0; j < 8; j++) f[j] = (n8 + j < V_SZ) ? wr[n8 + j] : 0.f;
    }
    __nv_bfloat162 p0 = __floats2bfloat162_rn(f[0], f[1]);
    __nv_bfloat162 p1 = __floats2bfloat162_rn(f[2], f[3]);
    __nv_bfloat162 p2 = __floats2bfloat162_rn(f[4], f[5]);
    __nv_bfloat162 p3 = __floats2bfloat162_rn(f[6], f[7]);
    uint4 v; v.x = *(unsigned*)&p0; v.y = *(unsigned*)&p1;
    v.z = *(unsigned*)&p2; v.w = *(unsigned*)&p3;
    *(uint4*)&g_wbf[(size_t)k * LDL + n8] = v;
}

// ===========================================================================
// K1: attention + concat input (R4-exact)
// ===========================================================================
__global__ void __launch_bounds__(256) attn_kernel(
    const float* __restrict__ emb, const float* __restrict__ h0,
    const float* __restrict__ enc, const float* __restrict__ attn_W,
    const float* __restrict__ attn_b, float* __restrict__ aw_out)
{
    __shared__ float sE[4][H_SZ];
    __shared__ float sH[4][H_SZ];
    __shared__ float sS[4][L_SZ];
    __shared__ float sP[4][4][L_SZ];

    int tid = threadIdx.x;
    int r0  = blockIdx.x * 4;

    for (int i = tid; i < 4 * H_SZ; i += 256) {
        int r = i >> 10, c = i & 1023;
        sE[r][c] = emb[(size_t)(r0 + r) * H_SZ + c];
        sH[r][c] = h0 [(size_t)(r0 + r) * H_SZ + c];
    }
    __syncthreads();

    {
        int l = tid & 63, gq = tid >> 6;
        float acc[4] = {0.f, 0.f, 0.f, 0.f};
        int kbeg = gq * 512, kend = kbeg + 512;
        for (int k = kbeg; k < kend; k++) {
            float w = attn_W[(size_t)k * L_SZ + l];
            if (k < H_SZ) {
                #pragma unroll
                for (int r = 0; r < 4; r++) acc[r] += sE[r][k] * w;
            } else {
                #pragma unroll
                for (int r = 0; r < 4; r++) acc[r] += sH[r][k - H_SZ] * w;
            }
        }
        #pragma unroll
        for (int r = 0; r < 4; r++) sP[gq][r][l] = acc[r];
    }
    __syncthreads();
    {
        int r = tid >> 6, l = tid & 63;
        sS[r][l] = sP[0][r][l] + sP[1][r][l] + sP[2][r][l] + sP[3][r][l] + attn_b[l];
    }
    __syncthreads();

    int warp = tid >> 5, lane = tid & 31;
    if (warp < 4) {
        int r = warp;
        float v0 = sS[r][lane], v1 = sS[r][lane + 32];
        float m = fmaxf(v0, v1);
        #pragma unroll
        for (int o = 16; o; o >>= 1) m = fmaxf(m, __shfl_xor_sync(0xffffffffu, m, o));
        float e0 = expf(v0 - m), e1 = expf(v1 - m);
        float s = e0 + e1;
        #pragma unroll
        for (int o = 16; o; o >>= 1) s += __shfl_xor_sync(0xffffffffu, s, o);
        float inv = 1.0f / s;
        float w0 = e0 * inv, w1 = e1 * inv;
        sS[r][lane] = w0; sS[r][lane + 32] = w1;
        if (aw_out) {
            aw_out[(size_t)(r0 + r) * L_SZ + lane]      = w0;
            aw_out[(size_t)(r0 + r) * L_SZ + lane + 32] = w1;
        }
    }
    __syncthreads();

    for (int cc = 0; cc < 4; cc++) {
        int h = cc * 256 + tid;
        float a[4] = {0.f, 0.f, 0.f, 0.f};
        for (int l = 0; l < L_SZ; l++) {
            float e = enc[(size_t)l * H_SZ + h];
            #pragma unroll
            for (int r = 0; r < 4; r++) a[r] += sS[r][l] * e;
        }
        #pragma unroll
        for (int r = 0; r < 4; r++) {
            g_xin[(size_t)(r0 + r) * (2 * H_SZ) + h]        = sE[r][h];
            g_xin[(size_t)(r0 + r) * (2 * H_SZ) + H_SZ + h] = a[r];
        }
    }
}

// ===========================================================================
// tf32 mma GEMM core (R4 body + split-K range [kbeg, kbeg+klen); null bias ok)
// ===========================================================================
__device__ __forceinline__ void gemm_tf32_core(
    float (*sA)[64][20], float (*sB)[64][20],
    const float* __restrict__ A, const float* __restrict__ Bm,
    const float* __restrict__ bias, float* __restrict__ C,
    int N, int Kstride, int kbeg, int klen,
    int b_kmajor, int relu, int bm0, int bn0)
{
    int tid = threadIdx.x;
    int warp = tid >> 5, lane = tid & 31, g = lane >> 2, q = lane & 3;
    int wm = warp & 1, wn = warp >> 1;

    int lr = tid >> 2, lc4 = (tid & 3) * 4;
    int tkr = tid >> 4, tc4 = (tid & 15) * 4;

    float acc[2][2][4];
    #pragma unroll
    for (int i = 0; i < 2; i++)
        #pragma unroll
        for (int j = 0; j < 2; j++)
            #pragma unroll
            for (int t = 0; t < 4; t++) acc[i][j][t] = 0.f;

    const int NS = klen / 16;
    {
        cp_async16_ca(smem_u32(&sA[0][lr][lc4]),
                      A + (size_t)(bm0 + lr) * Kstride + kbeg + lc4);
        if (b_kmajor) {
            cp_async16_cg(smem_u32(&sB[0][lr][lc4]),
                          Bm + (size_t)(bn0 + lr) * Kstride + kbeg + lc4);
        } else {
            float4 v = *(const float4*)(Bm + (size_t)(kbeg + tkr) * N + bn0 + tc4);
            sB[0][tc4][tkr] = v.x; sB[0][tc4 + 1][tkr] = v.y;
            sB[0][tc4 + 2][tkr] = v.z; sB[0][tc4 + 3][tkr] = v.w;
        }
        cp_commit();
    }

    for (int ks = 0; ks < NS; ks++) {
        int buf = ks & 1;
        bool hasNext = (ks + 1) < NS;
        cp_wait<0>();
        __syncthreads();
        float4 vB;
        if (hasNext) {
            int k0 = kbeg + (ks + 1) * 16;
            int nb = buf ^ 1;
            cp_async16_ca(smem_u32(&sA[nb][lr][lc4]),
                          A + (size_t)(bm0 + lr) * Kstride + k0 + lc4);
            if (b_kmajor)
                cp_async16_cg(smem_u32(&sB[nb][lr][lc4]),
                              Bm + (size_t)(bn0 + lr) * Kstride + k0 + lc4);
            else
                vB = *(const float4*)(Bm + (size_t)(k0 + tkr) * N + bn0 + tc4);
            cp_commit();
        }

        #pragma unroll
        for (int kk = 0; kk < 2; kk++) {
            int ko = kk * 8;
            unsigned a[2][4], b[2][2];
            #pragma unroll
            for (int mt = 0; mt < 2; mt++) {
                int rm = wm * 32 + mt * 16;
                a[mt][0] = __float_as_uint(sA[buf][rm + g][ko + q]);
                a[mt][1] = __float_as_uint(sA[buf][rm + g + 8][ko + q]);
                a[mt][2] = __float_as_uint(sA[buf][rm + g][ko + q + 4]);
                a[mt][3] = __float_as_uint(sA[buf][rm + g + 8][ko + q + 4]);
            }
            #pragma unroll
            for (int nt = 0; nt < 2; nt++) {
                int cn = wn * 16 + nt * 8 + g;
                b[nt][0] = __float_as_uint(sB[buf][cn][ko + q]);
                b[nt][1] = __float_as_uint(sB[buf][cn][ko + q + 4]);
            }
            #pragma unroll
            for (int mt = 0; mt < 2; mt++)
                #pragma unroll
                for (int nt = 0; nt < 2; nt++)
                    asm volatile(
                        "mma.sync.aligned.m16n8k8.row.col.f32.tf32.tf32.f32 "
                        "{%0,%1,%2,%3}, {%4,%5,%6,%7}, {%8,%9}, {%0,%1,%2,%3};"
                        : "+f"(acc[mt][nt][0]), "+f"(acc[mt][nt][1]),
                          "+f"(acc[mt][nt][2]), "+f"(acc[mt][nt][3])
                        : "r"(a[mt][0]), "r"(a[mt][1]), "r"(a[mt][2]), "r"(a[mt][3]),
                          "r"(b[nt][0]), "r"(b[nt][1]));
        }

        if (hasNext && !b_kmajor) {
            int nb = buf ^ 1;
            sB[nb][tc4][tkr] = vB.x; sB[nb][tc4 + 1][tkr] = vB.y;
            sB[nb][tc4 + 2][tkr] = vB.z; sB[nb][tc4 + 3][tkr] = vB.w;
        }
    }

    #pragma unroll
    for (int mt = 0; mt < 2; mt++) {
        int row = bm0 + wm * 32 + mt * 16 + g;
        #pragma unroll
        for (int nt = 0; nt < 2; nt++) {
            int col = bn0 + wn * 16 + nt * 8 + 2 * q;
            float b0 = bias ? bias[col]     : 0.f;
            float b1 = bias ? bias[col + 1] : 0.f;
            float v0 = acc[mt][nt][0] + b0, v1 = acc[mt][nt][1] + b1;
            float v2 = acc[mt][nt][2] + b0, v3 = acc[mt][nt][3] + b1;
            if (relu) {
                v0 = fmaxf(v0, 0.f); v1 = fmaxf(v1, 0.f);
                v2 = fmaxf(v2, 0.f); v3 = fmaxf(v3, 0.f);
            }
            C[(size_t)row * N + col] = v0;       C[(size_t)row * N + col + 1] = v1;
            C[(size_t)(row + 8) * N + col] = v2; C[(size_t)(row + 8) * N + col + 1] = v3;
        }
    }
}

// ===========================================================================
// K2: comb (blocks 0..127, full K=2048) + ghh split-K x2 (blocks 128..895)
// ===========================================================================
__global__ void __launch_bounds__(256) comb_ghh_kernel(
    const float* __restrict__ comb_W, const float* __restrict__ comb_b,
    const float* __restrict__ h0, const float* __restrict__ W_hh,
    const float* __restrict__ b_hh)
{
    __shared__ float sA[2][64][20];
    __shared__ float sB[2][64][20];
    int bid = blockIdx.x;
    if (bid < 128) {
        gemm_tf32_core(sA, sB, g_xin, comb_W, comb_b, g_x,
                       H_SZ, 2 * H_SZ, 0, 2 * H_SZ, 0, 1,
                       (bid & 7) * 64, (bid >> 3) * 64);
    } else {
        int t = bid - 128;             // 0..767
        int part = t & 1;
        int r = t >> 1;                // 0..383
        float* out = part ? g_gh1 : g_gh0;
        const float* bb = part ? nullptr : b_hh;
        gemm_tf32_core(sA, sB, h0, W_hh, bb, out,
                       3 * H_SZ, H_SZ, part * 512, 512, 1, 0,
                       (r & 7) * 64, (r >> 3) * 64);
    }
}

// ===========================================================================
// K3: gih split-K x2 (768 blocks)
// ===========================================================================
__global__ void __launch_bounds__(256) gemm_gih_kernel(
    const float* __restrict__ W_ih, const float* __restrict__ b_ih)
{
    __shared__ float sA[2][64][20];
    __shared__ float sB[2][64][20];
    int t = blockIdx.x;                // 0..767
    int part = t & 1;
    int r = t >> 1;                    // 0..383
    float* out = part ? g_gi1 : g_gi0;
    const float* bb = part ? nullptr : b_ih;
    gemm_tf32_core(sA, sB, g_x, W_ih, bb, out,
                   3 * H_SZ, H_SZ, part * 512, 512, 1, 0,
                   (r & 7) * 64, (r >> 3) * 64);
}

// ===========================================================================
// K4: GRU elementwise (sums split-K parts)
// ===========================================================================
__global__ void __launch_bounds__(256) gru_kernel(
    const float* __restrict__ h0, float* __restrict__ h1_extra)
{
    int idx = blockIdx.x * 256 + threadIdx.x;
    if (idx >= B_SZ * H_SZ) return;
    int row = idx >> 10, j = idx & 1023;
    size_t base = (size_t)row * 3 * H_SZ;
    float gi_r = g_gi0[base + j]            + g_gi1[base + j];
    float gi_z = g_gi0[base + H_SZ + j]     + g_gi1[base + H_SZ + j];
    float gi_n = g_gi0[base + 2 * H_SZ + j] + g_gi1[base + 2 * H_SZ + j];
    float gh_r = g_gh0[base + j]            + g_gh1[base + j];
    float gh_z = g_gh0[base + H_SZ + j]     + g_gh1[base + H_SZ + j];
    float gh_n = g_gh0[base + 2 * H_SZ + j] + g_gh1[base + 2 * H_SZ + j];
    float rg = 1.f / (1.f + expf(-(gi_r + gh_r)));
    float zg = 1.f / (1.f + expf(-(gi_z + gh_z)));
    float ng = tanhf(gi_n + rg * gh_n);
    float h0v = h0[idx];
    float h1 = (1.f - zg) * ng + zg * h0v;
    g_h1b[idx] = __float2bfloat16(h1);
    if (h1_extra) h1_extra[idx] = h1;
}

// ===========================================================================
// K5: vocab GEMM (R10-measured 201us: 128x128x32, 5-stage cp.async, 2 CTA/SM),
//   fp16 logits + per-(row,n-tile) (max,sumexp) partials.
// ===========================================================================
#define OUT_STAGES 5
#define A_STAGE_B  8192
#define B_STAGE_B  8192

__global__ void __launch_bounds__(256, 2) gemm_out_kernel(
    const float* __restrict__ bias)
{
    extern __shared__ __nv_bfloat16 dynsmem[];
    __shared__ float2 spart[128][4];

    const int K = 1024;
    int tid = threadIdx.x;
    int warp = tid >> 5, lane = tid & 31, g = lane >> 2, q = lane & 3;
    int wm = warp & 1, wn = warp >> 1;
    int bm0 = blockIdx.x * 128, bn0 = blockIdx.y * 128;

    uint32_t smem_b = smem_u32(dynsmem);
    uint32_t sB_b   = smem_b + OUT_STAGES * A_STAGE_B;

    int a_r0 = tid >> 2,  a_c0 = tid & 3;
    int b_k0 = tid >> 4,  b_c0 = tid & 15;
    uint32_t a_dst0 = a_r0 * 64 + ((a_c0 ^ ((a_r0 >> 1) & 3)) << 4);
    uint32_t a_dst1 = (a_r0 + 64) * 64 + ((a_c0 ^ (((a_r0 + 64) >> 1) & 3)) << 4);
    uint32_t b_dst0 = b_k0 * 256 + ((b_c0 ^ (b_k0 & 7)) << 4);
    uint32_t b_dst1 = (b_k0 + 16) * 256 + ((b_c0 ^ ((b_k0 + 16) & 7)) << 4);
    const __nv_bfloat16* a_src0 = g_h1b + (size_t)(bm0 + a_r0) * K + a_c0 * 8;
    const __nv_bfloat16* a_src1 = g_h1b + (size_t)(bm0 + a_r0 + 64) * K + a_c0 * 8;
    const __nv_bfloat16* b_src0 = g_wbf + (size_t)b_k0 * LDL + bn0 + b_c0 * 8;
    const __nv_bfloat16* b_src1 = g_wbf + (size_t)(b_k0 + 16) * LDL + bn0 + b_c0 * 8;

    int a_row[4];
    #pragma unroll
    for (int mt = 0; mt < 4; mt++) a_row[mt] = wm * 64 + mt * 16 + (lane & 15);
    int b_lk = lane & 15, b_lc = lane >> 4;

    float acc[4][4][4];
    #pragma unroll
    for (int i = 0; i < 4; i++)
        #pragma unroll
        for (int j = 0; j < 4; j++)
            #pragma unroll
            for (int t = 0; t < 4; t++) acc[i][j][t] = 0.f;

    #pragma unroll
    for (int st = 0; st < OUT_STAGES - 1; st++) {
        uint32_t ab = smem_b + st * A_STAGE_B;
        uint32_t bb = sB_b   + st * B_STAGE_B;
        int k0 = st * 32;
        cp_async16_ca(ab + a_dst0, a_src0 + k0);
        cp_async16_ca(ab + a_dst1, a_src1 + k0);
        cp_async16_cg(bb + b_dst0, b_src0 + (size_t)k0 * LDL);
        cp_async16_cg(bb + b_dst1, b_src1 + (size_t)k0 * LDL);
        cp_commit();
    }

    int slot = 0;
    for (int ks = 0; ks < 32; ks++) {
        cp_wait<OUT_STAGES - 2>();
        __syncthreads();

        uint32_t ab = smem_b + slot * A_STAGE_B;
        uint32_t bb = sB_b   + slot * B_STAGE_B;
        #pragma unroll
        for (int kk = 0; kk < 2; kk++) {
            unsigned a[4][4], b[4][2];
            #pragma unroll
            for (int mt = 0; mt < 4; mt++) {
                int chunk = kk * 2 + (lane >> 4);
                uint32_t addr = ab + a_row[mt] * 64 +
                                ((chunk ^ ((a_row[mt] >> 1) & 3)) << 4);
                LDMX4(a[mt][0], a[mt][1], a[mt][2], a[mt][3], addr);
            }
            #pragma unroll
            for (int h = 0; h < 2; h++) {
                int krow = kk * 16 + b_lk;
                int c = wn * 4 + 2 * h + b_lc;
                uint32_t addr = bb + krow * 256 + ((c ^ (krow & 7)) << 4);
                unsigned r0, r1, r2, r3;
                LDMX4T(r0, r1, r2, r3, addr);
                b[2 * h][0] = r0;     b[2 * h][1] = r1;
                b[2 * h + 1][0] = r2; b[2 * h + 1][1] = r3;
            }
            #pragma unroll
            for (int mt = 0; mt < 4; mt++)
                #pragma unroll
                for (int nt = 0; nt < 4; nt++)
                    asm volatile(
                        "mma.sync.aligned.m16n8k16.row.col.f32.bf16.bf16.f32 "
                        "{%0,%1,%2,%3}, {%4,%5,%6,%7}, {%8,%9}, {%0,%1,%2,%3};"
                        : "+f"(acc[mt][nt][0]), "+f"(acc[mt][nt][1]),
                          "+f"(acc[mt][nt][2]), "+f"(acc[mt][nt][3])
                        : "r"(a[mt][0]), "r"(a[mt][1]), "r"(a[mt][2]), "r"(a[mt][3]),
                          "r"(b[nt][0]), "r"(b[nt][1]));
        }

        int nst = ks + OUT_STAGES - 1;
        if (nst < 32) {
            int wslot = nst % OUT_STAGES;
            uint32_t ab2 = smem_b + wslot * A_STAGE_B;
            uint32_t bb2 = sB_b   + wslot * B_STAGE_B;
            int k0 = nst * 32;
            cp_async16_ca(ab2 + a_dst0, a_src0 + k0);
            cp_async16_ca(ab2 + a_dst1, a_src1 + k0);
            cp_async16_cg(bb2 + b_dst0, b_src0 + (size_t)k0 * LDL);
            cp_async16_cg(bb2 + b_dst1, b_src1 + (size_t)k0 * LDL);
            cp_commit();
        }
        slot = (slot + 1 == OUT_STAGES) ? 0 : slot + 1;
    }

    // ---- epilogue: bias, fp16 logits, (max,sumexp) partials ----
    #pragma unroll
    for (int mt = 0; mt < 4; mt++) {
        int row = bm0 + wm * 64 + mt * 16 + g;
        #pragma unroll
        for (int nt = 0; nt < 4; nt++) {
            int col = bn0 + wn * 32 + nt * 8 + 2 * q;
            float b0 = (col < V_SZ)     ? bias[col]     : 0.f;
            float b1 = (col + 1 < V_SZ) ? bias[col + 1] : 0.f;
            acc[mt][nt][0] = (col < V_SZ)     ? acc[mt][nt][0] + b0 : -1e38f;
            acc[mt][nt][1] = (col + 1 < V_SZ) ? acc[mt][nt][1] + b1 : -1e38f;
            acc[mt][nt][2] = (col < V_SZ)     ? acc[mt][nt][2] + b0 : -1e38f;
            acc[mt][nt][3] = (col + 1 < V_SZ) ? acc[mt][nt][3] + b1 : -1e38f;
            *(__half2*)(g_logith + (size_t)row * LDL + col) =
                __floats2half2_rn(acc[mt][nt][0], acc[mt][nt][1]);
            *(__half2*)(g_logith + (size_t)(row + 8) * LDL + col) =
                __floats2half2_rn(acc[mt][nt][2], acc[mt][nt][3]);
        }
    }

    #pragma unroll
    for (int mt = 0; mt < 4; mt++) {
        #pragma unroll
        for (int half = 0; half < 2; half++) {
            int lr = wm * 64 + mt * 16 + g + 8 * half;
            float mx = -1e38f, sm = 0.f;
            #pragma unroll
            for (int nt = 0; nt < 4; nt++)
                mx = fmaxf(mx, fmaxf(acc[mt][nt][2 * half], acc[mt][nt][2 * half + 1]));
            #pragma unroll
            for (int nt = 0; nt < 4; nt++) {
                float v0 = acc[mt][nt][2 * half], v1 = acc[mt][nt][2 * half + 1];
                if (v0 > -1e37f) sm += expf(v0 - mx);
                if (v1 > -1e37f) sm += expf(v1 - mx);
            }
            #pragma unroll
            for (int o = 1; o <= 2; o <<= 1) {
                float mo = __shfl_xor_sync(0xffffffffu, mx, o);
                float so = __shfl_xor_sync(0xffffffffu, sm, o);
                float mn = fmaxf(mx, mo);
                sm = safe_scale(sm, mx, mn) + safe_scale(so, mo, mn);
                mx = mn;
            }
            if (q == 0) spart[lr][wn] = make_float2(mx, sm);
        }
    }
    __syncthreads();
    if (tid < 128) {
        float mx = -1e38f, sm = 0.f;
        #pragma unroll
        for (int w = 0; w < 4; w++) {
            float2 p = spart[tid][w];
            float mn = fmaxf(mx, p.x);
            sm = safe_scale(sm, mx, mn) + safe_scale(p.y, p.x, mn);
            mx = mn;
        }
        g_part[(size_t)(bm0 + tid) * 400 + blockIdx.y] = make_float2(mx, sm);
    }
}

// ===========================================================================
// K6: log_softmax from partials; 2 blocks per row (half-row each).
// ===========================================================================
__global__ void __launch_bounds__(256) lsm_kernel(float* __restrict__ outp)
{
    __shared__ float sredm[8];
    __shared__ float sreds[8];
    int row = blockIdx.x >> 1, halfb = blockIdx.x & 1;
    int tid = threadIdx.x, lane = tid & 31, warp = tid >> 5;

    float m = -1e38f, s = 0.f;
    for (int i = tid; i < NB_T; i += 256) {
        float2 p = g_part[(size_t)row * 400 + i];
        float mn = fmaxf(m, p.x);
        s = safe_scale(s, m, mn) + safe_scale(p.y, p.x, mn);
        m = mn;
    }
    #pragma unroll
    for (int o = 16; o; o >>= 1) {
        float mo = __shfl_xor_sync(0xffffffffu, m, o);
        float so = __shfl_xor_sync(0xffffffffu, s, o);
        float mn = fmaxf(m, mo);
        s = safe_scale(s, m, mn) + safe_scale(so, mo, mn);
        m = mn;
    }
    if (lane == 0) { sredm[warp] = m; sreds[warp] = s; }
    __syncthreads();
    float mall = sredm[0];
    #pragma unroll
    for (int i = 1; i < 8; i++) mall = fmaxf(mall, sredm[i]);
    float tot = 0.f;
    #pragma unroll
    for (int i = 0; i < 8; i++) tot += safe_scale(sreds[i], sredm[i], mall);
    float lse = mall + logf(tot);

    const __half* lg = g_logith + (size_t)row * LDL;
    float* op = outp + (size_t)row * V_SZ;
    const int HALF = 25128;            // multiple of 8
    int vbeg = halfb ? HALF : 0;
    int vend = halfb ? V_SZ : HALF;
    for (int v = vbeg + tid * 8; v + 7 < vend; v += 2048) {
        uint4 raw = *(const uint4*)(lg + v);
        float2 f0 = __half22float2(*(__half2*)&raw.x);
        float2 f1 = __half22float2(*(__half2*)&raw.y);
        float2 f2 = __half22float2(*(__half2*)&raw.z);
        float2 f3 = __half22float2(*(__half2*)&raw.w);
        op[v]     = f0.x - lse; op[v + 1] = f0.y - lse;
        op[v + 2] = f1.x - lse; op[v + 3] = f1.y - lse;
        op[v + 4] = f2.x - lse; op[v + 5] = f2.y - lse;
        op[v + 6] = f3.x - lse; op[v + 7] = f3.y - lse;
    }
    if (halfb && tid < 16) {
        int v = 50248 + tid;           // tail 50248..50256
        if (v < V_SZ) op[v] = __half2float(lg[v]) - lse;
    }
}

// ===========================================================================
// host launcher
// ===========================================================================
extern "C" void kernel_launch(void* const* d_in, const int* in_sizes, int n_in,
                              void* d_out, int out_size)
{
    const float* input_emb = (const float*)d_in[0];
    const float* hidden    = (const float*)d_in[1];
    const float* enc       = (const float*)d_in[2];
    const float* attn_W    = (const float*)d_in[3];
    const float* attn_b    = (const float*)d_in[4];
    const float* comb_W    = (const float*)d_in[5];
    const float* comb_b    = (const float*)d_in[6];
    const float* W_ih      = (const float*)d_in[7];
    const float* W_hh      = (const float*)d_in[8];
    const float* b_ih      = (const float*)d_in[9];
    const float* b_hh      = (const float*)d_in[10];
    const float* out_W     = (const float*)d_in[11];
    const float* out_b     = (const float*)d_in[12];

    float* outp = (float*)d_out;
    long long osz = (long long)out_size;
    const long long OV = (long long)B_SZ * V_SZ;
    float* h1_out = (osz >= OV + (long long)B_SZ * H_SZ)
                        ? outp + (size_t)OV : nullptr;
    float* aw_out = (osz >= OV + (long long)B_SZ * H_SZ + (long long)B_SZ * L_SZ)
                        ? outp + (size_t)OV + (size_t)B_SZ * H_SZ : nullptr;

    const int OUT_SMEM = OUT_STAGES * (A_STAGE_B + B_STAGE_B);   // 80KB
    cudaFuncSetAttribute(gemm_out_kernel,
                         cudaFuncAttributeMaxDynamicSharedMemorySize, OUT_SMEM);

    // K0: W -> bf16 padded
    convw_kernel<<<(H_SZ * (LDL / 8)) / 256, 256>>>(out_W);
    // K1: attention + concat
    attn_kernel<<<B_SZ / 4, 256>>>(input_emb, hidden, enc, attn_W, attn_b, aw_out);
    // K2: comb (128) + ghh split-K x2 (768)
    comb_ghh_kernel<<<896, 256>>>(comb_W, comb_b, hidden, W_hh, b_hh);
    // K3: gih split-K x2 (768)
    gemm_gih_kernel<<<768, 256>>>(W_ih, b_ih);
    // K4: GRU (sums parts)
    gru_kernel<<<(B_SZ * H_SZ) / 256, 256>>>(hidden, h1_out);
    // K5: vocab GEMM
    {
        dim3 grid(B_SZ / 128, NB_T);   // m fastest -> L2 reuse of W tiles
        gemm_out_kernel<<<grid, 256, OUT_SMEM>>>(out_b);
    }
    // K6: log_softmax (2 blocks/row)
    lsm_kernel<<<2 * B_SZ, 256>>>(outp);
}

// round 15
// speedup vs baseline: 1.1751x; 1.1666x over previous
#include <cuda_runtime.h>
#include <cuda_bf16.h>
#include <cstdint>

#define B_SZ 512
#define H_SZ 1024
#define L_SZ 64
#define V_SZ 50257
#define LDL  50304   // padded logits / W row stride (128*393)
#define NB_T 393     // 128-wide n-tiles in vocab GEMM

// ---------------- scratch (device globals; no allocation allowed) ----------
__device__ float g_xin[B_SZ * 2 * H_SZ];
__device__ float g_x[B_SZ * H_SZ];
__device__ float g_gi[B_SZ * 3 * H_SZ];
__device__ float g_gh[B_SZ * 3 * H_SZ];
__device__ __nv_bfloat16 g_h1b[B_SZ * H_SZ];
__device__ __nv_bfloat16 g_wbf[(size_t)H_SZ * LDL];   // bf16 W k-major, padded
__device__ float g_logits[(size_t)B_SZ * LDL];
__device__ float2 g_part[B_SZ * 400];

// ---------------- helpers ----------------
__device__ __forceinline__ void cp_async16_cg(uint32_t dst, const void* src) {
    asm volatile("cp.async.cg.shared.global [%0], [%1], 16;" :: "r"(dst), "l"(src));
}
__device__ __forceinline__ void cp_async16_ca(uint32_t dst, const void* src) {
    asm volatile("cp.async.ca.shared.global [%0], [%1], 16;" :: "r"(dst), "l"(src));
}
__device__ __forceinline__ void cp_commit() {
    asm volatile("cp.async.commit_group;");
}
template <int N>
__device__ __forceinline__ void cp_wait() {
    asm volatile("cp.async.wait_group %0;" :: "n"(N));
}
__device__ __forceinline__ uint32_t smem_u32(const void* p) {
    return (uint32_t)__cvta_generic_to_shared(p);
}
#define LDMX4(R0,R1,R2,R3,ADDR) \
    asm volatile("ldmatrix.sync.aligned.m8n8.x4.shared.b16 {%0,%1,%2,%3}, [%4];" \
        : "=r"(R0), "=r"(R1), "=r"(R2), "=r"(R3) : "r"(ADDR))
#define LDMX4T(R0,R1,R2,R3,ADDR) \
    asm volatile("ldmatrix.sync.aligned.m8n8.x4.trans.shared.b16 {%0,%1,%2,%3}, [%4];" \
        : "=r"(R0), "=r"(R1), "=r"(R2), "=r"(R3) : "r"(ADDR))

__device__ __forceinline__ float safe_scale(float s, float m, float mn) {
    return (m > -1e37f) ? s * expf(m - mn) : 0.f;
}

// ===========================================================================
// K0: attn (blocks 0..127) + convw (blocks 128..)  [verified passing in R10]
//   attn: smem-compute heavy; convw: pure DRAM stream.
// ===========================================================================
__global__ void __launch_bounds__(256) attn_convw_kernel(
    const float* __restrict__ emb, const float* __restrict__ h0,
    const float* __restrict__ enc, const float* __restrict__ attn_W,
    const float* __restrict__ attn_b, float* __restrict__ aw_out,
    const float* __restrict__ W)
{
    __shared__ float sE[4][H_SZ];
    __shared__ float sH[4][H_SZ];
    __shared__ float sS[4][L_SZ];
    __shared__ float sP[4][4][L_SZ];

    int tid = threadIdx.x;

    if (blockIdx.x >= 128) {
        // ---- convw: out_W fp32 -> g_wbf bf16 padded k-major ----
        size_t id = (size_t)(blockIdx.x - 128) * 256 + tid;
        int k  = (int)(id / (LDL / 8));
        int n8 = (int)(id % (LDL / 8)) * 8;
        const float* wr = W + (size_t)k * V_SZ;
        float f[8];
        if (n8 + 7 < V_SZ) {
            #pragma unroll
            for (int j = 0; j < 8; j++) f[j] = wr[n8 + j];
        } else {
            #pragma unroll
            for (int j = 0; j < 8; j++) f[j] = (n8 + j < V_SZ) ? wr[n8 + j] : 0.f;
        }
        __nv_bfloat162 p0 = __floats2bfloat162_rn(f[0], f[1]);
        __nv_bfloat162 p1 = __floats2bfloat162_rn(f[2], f[3]);
        __nv_bfloat162 p2 = __floats2bfloat162_rn(f[4], f[5]);
        __nv_bfloat162 p3 = __floats2bfloat162_rn(f[6], f[7]);
        uint4 v; v.x = *(unsigned*)&p0; v.y = *(unsigned*)&p1;
        v.z = *(unsigned*)&p2; v.w = *(unsigned*)&p3;
        *(uint4*)&g_wbf[(size_t)k * LDL + n8] = v;
        return;
    }

    // ---- attention ----
    int r0 = blockIdx.x * 4;

    for (int i = tid; i < 4 * H_SZ; i += 256) {
        int r = i >> 10, c = i & 1023;
        sE[r][c] = emb[(size_t)(r0 + r) * H_SZ + c];
        sH[r][c] = h0 [(size_t)(r0 + r) * H_SZ + c];
    }
    __syncthreads();

    {
        int l = tid & 63, gq = tid >> 6;
        float acc[4] = {0.f, 0.f, 0.f, 0.f};
        int kbeg = gq * 512, kend = kbeg + 512;
        for (int k = kbeg; k < kend; k++) {
            float w = attn_W[(size_t)k * L_SZ + l];
            if (k < H_SZ) {
                #pragma unroll
                for (int r = 0; r < 4; r++) acc[r] += sE[r][k] * w;
            } else {
                #pragma unroll
                for (int r = 0; r < 4; r++) acc[r] += sH[r][k - H_SZ] * w;
            }
        }
        #pragma unroll
        for (int r = 0; r < 4; r++) sP[gq][r][l] = acc[r];
    }
    __syncthreads();
    {
        int r = tid >> 6, l = tid & 63;
        sS[r][l] = sP[0][r][l] + sP[1][r][l] + sP[2][r][l] + sP[3][r][l] + attn_b[l];
    }
    __syncthreads();

    int warp = tid >> 5, lane = tid & 31;
    if (warp < 4) {
        int r = warp;
        float v0 = sS[r][lane], v1 = sS[r][lane + 32];
        float m = fmaxf(v0, v1);
        #pragma unroll
        for (int o = 16; o; o >>= 1) m = fmaxf(m, __shfl_xor_sync(0xffffffffu, m, o));
        float e0 = expf(v0 - m), e1 = expf(v1 - m);
        float s = e0 + e1;
        #pragma unroll
        for (int o = 16; o; o >>= 1) s += __shfl_xor_sync(0xffffffffu, s, o);
        float inv = 1.0f / s;
        float w0 = e0 * inv, w1 = e1 * inv;
        sS[r][lane] = w0; sS[r][lane + 32] = w1;
        if (aw_out) {
            aw_out[(size_t)(r0 + r) * L_SZ + lane]      = w0;
            aw_out[(size_t)(r0 + r) * L_SZ + lane + 32] = w1;
        }
    }
    __syncthreads();

    for (int cc = 0; cc < 4; cc++) {
        int h = cc * 256 + tid;
        float a[4] = {0.f, 0.f, 0.f, 0.f};
        for (int l = 0; l < L_SZ; l++) {
            float e = enc[(size_t)l * H_SZ + h];
            #pragma unroll
            for (int r = 0; r < 4; r++) a[r] += sS[r][l] * e;
        }
        #pragma unroll
        for (int r = 0; r < 4; r++) {
            g_xin[(size_t)(r0 + r) * (2 * H_SZ) + h]        = sE[r][h];
            g_xin[(size_t)(r0 + r) * (2 * H_SZ) + H_SZ + h] = a[r];
        }
    }
}

// ===========================================================================
// tf32 mma GEMM core (R4-exact: kstep 16, 2-stage cp.async)
// ===========================================================================
__device__ __forceinline__ void gemm_tf32_core(
    float (*sA)[64][20], float (*sB)[64][20],
    const float* __restrict__ A, const float* __restrict__ Bm,
    const float* __restrict__ bias, float* __restrict__ C,
    int N, int K, int b_kmajor, int relu, int bm0, int bn0)
{
    int tid = threadIdx.x;
    int warp = tid >> 5, lane = tid & 31, g = lane >> 2, q = lane & 3;
    int wm = warp & 1, wn = warp >> 1;

    int lr = tid >> 2, lc4 = (tid & 3) * 4;
    int tkr = tid >> 4, tc4 = (tid & 15) * 4;

    float acc[2][2][4];
    #pragma unroll
    for (int i = 0; i < 2; i++)
        #pragma unroll
        for (int j = 0; j < 2; j++)
            #pragma unroll
            for (int t = 0; t < 4; t++) acc[i][j][t] = 0.f;

    const int NS = K / 16;
    {
        cp_async16_ca(smem_u32(&sA[0][lr][lc4]), A + (size_t)(bm0 + lr) * K + lc4);
        if (b_kmajor) {
            cp_async16_cg(smem_u32(&sB[0][lr][lc4]), Bm + (size_t)(bn0 + lr) * K + lc4);
        } else {
            float4 v = *(const float4*)(Bm + (size_t)tkr * N + bn0 + tc4);
            sB[0][tc4][tkr] = v.x; sB[0][tc4 + 1][tkr] = v.y;
            sB[0][tc4 + 2][tkr] = v.z; sB[0][tc4 + 3][tkr] = v.w;
        }
        cp_commit();
    }

    for (int ks = 0; ks < NS; ks++) {
        int buf = ks & 1;
        bool hasNext = (ks + 1) < NS;
        cp_wait<0>();
        __syncthreads();
        float4 vB;
        if (hasNext) {
            int k0 = (ks + 1) * 16;
            int nb = buf ^ 1;
            cp_async16_ca(smem_u32(&sA[nb][lr][lc4]),
                          A + (size_t)(bm0 + lr) * K + k0 + lc4);
            if (b_kmajor)
                cp_async16_cg(smem_u32(&sB[nb][lr][lc4]),
                              Bm + (size_t)(bn0 + lr) * K + k0 + lc4);
            else
                vB = *(const float4*)(Bm + (size_t)(k0 + tkr) * N + bn0 + tc4);
            cp_commit();
        }

        #pragma unroll
        for (int kk = 0; kk < 2; kk++) {
            int ko = kk * 8;
            unsigned a[2][4], b[2][2];
            #pragma unroll
            for (int mt = 0; mt < 2; mt++) {
                int rm = wm * 32 + mt * 16;
                a[mt][0] = __float_as_uint(sA[buf][rm + g][ko + q]);
                a[mt][1] = __float_as_uint(sA[buf][rm + g + 8][ko + q]);
                a[mt][2] = __float_as_uint(sA[buf][rm + g][ko + q + 4]);
                a[mt][3] = __float_as_uint(sA[buf][rm + g + 8][ko + q + 4]);
            }
            #pragma unroll
            for (int nt = 0; nt < 2; nt++) {
                int cn = wn * 16 + nt * 8 + g;
                b[nt][0] = __float_as_uint(sB[buf][cn][ko + q]);
                b[nt][1] = __float_as_uint(sB[buf][cn][ko + q + 4]);
            }
            #pragma unroll
            for (int mt = 0; mt < 2; mt++)
                #pragma unroll
                for (int nt = 0; nt < 2; nt++)
                    asm volatile(
                        "mma.sync.aligned.m16n8k8.row.col.f32.tf32.tf32.f32 "
                        "{%0,%1,%2,%3}, {%4,%5,%6,%7}, {%8,%9}, {%0,%1,%2,%3};"
                        : "+f"(acc[mt][nt][0]), "+f"(acc[mt][nt][1]),
                          "+f"(acc[mt][nt][2]), "+f"(acc[mt][nt][3])
                        : "r"(a[mt][0]), "r"(a[mt][1]), "r"(a[mt][2]), "r"(a[mt][3]),
                          "r"(b[nt][0]), "r"(b[nt][1]));
        }

        if (hasNext && !b_kmajor) {
            int nb = buf ^ 1;
            sB[nb][tc4][tkr] = vB.x; sB[nb][tc4 + 1][tkr] = vB.y;
            sB[nb][tc4 + 2][tkr] = vB.z; sB[nb][tc4 + 3][tkr] = vB.w;
        }
    }

    #pragma unroll
    for (int mt = 0; mt < 2; mt++) {
        int row = bm0 + wm * 32 + mt * 16 + g;
        #pragma unroll
        for (int nt = 0; nt < 2; nt++) {
            int col = bn0 + wn * 16 + nt * 8 + 2 * q;
            float b0 = bias[col], b1 = bias[col + 1];
            float v0 = acc[mt][nt][0] + b0, v1 = acc[mt][nt][1] + b1;
            float v2 = acc[mt][nt][2] + b0, v3 = acc[mt][nt][3] + b1;
            if (relu) {
                v0 = fmaxf(v0, 0.f); v1 = fmaxf(v1, 0.f);
                v2 = fmaxf(v2, 0.f); v3 = fmaxf(v3, 0.f);
            }
            C[(size_t)row * N + col] = v0;       C[(size_t)row * N + col + 1] = v1;
            C[(size_t)(row + 8) * N + col] = v2; C[(size_t)(row + 8) * N + col + 1] = v3;
        }
    }
}

__global__ void __launch_bounds__(256) comb_ghh_kernel(
    const float* __restrict__ comb_W, const float* __restrict__ comb_b,
    const float* __restrict__ h0, const float* __restrict__ W_hh,
    const float* __restrict__ b_hh)
{
    __shared__ float sA[2][64][20];
    __shared__ float sB[2][64][20];
    if (blockIdx.z == 0) {
        gemm_tf32_core(sA, sB, g_xin, comb_W, comb_b, g_x,
                       H_SZ, 2 * H_SZ, 0, 1, blockIdx.x * 64, blockIdx.y * 64);
    } else {
        int bn = (blockIdx.z - 1) * 16 + blockIdx.y;
        gemm_tf32_core(sA, sB, h0, W_hh, b_hh, g_gh,
                       3 * H_SZ, H_SZ, 1, 0, blockIdx.x * 64, bn * 64);
    }
}
__global__ void __launch_bounds__(256) gemm_gih_kernel(
    const float* __restrict__ W_ih, const float* __restrict__ b_ih)
{
    __shared__ float sA[2][64][20];
    __shared__ float sB[2][64][20];
    gemm_tf32_core(sA, sB, g_x, W_ih, b_ih, g_gi,
                   3 * H_SZ, H_SZ, 1, 0, blockIdx.x * 64, blockIdx.y * 64);
}

// ===========================================================================
// K3: GRU elementwise (R4-exact)
// ===========================================================================
__global__ void __launch_bounds__(256) gru_kernel(
    const float* __restrict__ h0, float* __restrict__ h1_extra)
{
    int idx = blockIdx.x * 256 + threadIdx.x;
    if (idx >= B_SZ * H_SZ) return;
    int row = idx >> 10, j = idx & 1023;
    const float* gi = g_gi + (size_t)row * 3 * H_SZ;
    const float* gh = g_gh + (size_t)row * 3 * H_SZ;
    float rg = 1.f / (1.f + expf(-(gi[j] + gh[j])));
    float zg = 1.f / (1.f + expf(-(gi[H_SZ + j] + gh[H_SZ + j])));
    float ng = tanhf(gi[2 * H_SZ + j] + rg * gh[2 * H_SZ + j]);
    float h0v = h0[idx];
    float h1 = (1.f - zg) * ng + zg * h0v;
    g_h1b[idx] = __float2bfloat16(h1);
    if (h1_extra) h1_extra[idx] = h1;
}

// ===========================================================================
// K4: vocab GEMM (R4-exact: 128x128x32, 5-stage cp.async, 2 CTA/SM),
//   fp32 logits + per-(row,n-tile) (max,sumexp) partials.
// ===========================================================================
#define OUT_STAGES 5
#define A_STAGE_B  8192
#define B_STAGE_B  8192

__global__ void __launch_bounds__(256, 2) gemm_out_kernel(
    const float* __restrict__ bias)
{
    extern __shared__ __nv_bfloat16 dynsmem[];
    __shared__ float2 spart[128][4];

    const int K = 1024;
    int tid = threadIdx.x;
    int warp = tid >> 5, lane = tid & 31, g = lane >> 2, q = lane & 3;
    int wm = warp & 1, wn = warp >> 1;
    int bm0 = blockIdx.x * 128, bn0 = blockIdx.y * 128;

    uint32_t smem_b = smem_u32(dynsmem);
    uint32_t sB_b   = smem_b + OUT_STAGES * A_STAGE_B;

    int a_r0 = tid >> 2,  a_c0 = tid & 3;
    int b_k0 = tid >> 4,  b_c0 = tid & 15;
    uint32_t a_dst0 = a_r0 * 64 + ((a_c0 ^ ((a_r0 >> 1) & 3)) << 4);
    uint32_t a_dst1 = (a_r0 + 64) * 64 + ((a_c0 ^ (((a_r0 + 64) >> 1) & 3)) << 4);
    uint32_t b_dst0 = b_k0 * 256 + ((b_c0 ^ (b_k0 & 7)) << 4);
    uint32_t b_dst1 = (b_k0 + 16) * 256 + ((b_c0 ^ ((b_k0 + 16) & 7)) << 4);
    const __nv_bfloat16* a_src0 = g_h1b + (size_t)(bm0 + a_r0) * K + a_c0 * 8;
    const __nv_bfloat16* a_src1 = g_h1b + (size_t)(bm0 + a_r0 + 64) * K + a_c0 * 8;
    const __nv_bfloat16* b_src0 = g_wbf + (size_t)b_k0 * LDL + bn0 + b_c0 * 8;
    const __nv_bfloat16* b_src1 = g_wbf + (size_t)(b_k0 + 16) * LDL + bn0 + b_c0 * 8;

    int a_row[4];
    #pragma unroll
    for (int mt = 0; mt < 4; mt++) a_row[mt] = wm * 64 + mt * 16 + (lane & 15);
    int b_lk = lane & 15, b_lc = lane >> 4;

    float acc[4][4][4];
    #pragma unroll
    for (int i = 0; i < 4; i++)
        #pragma unroll
        for (int j = 0; j < 4; j++)
            #pragma unroll
            for (int t = 0; t < 4; t++) acc[i][j][t] = 0.f;

    #pragma unroll
    for (int st = 0; st < OUT_STAGES - 1; st++) {
        uint32_t ab = smem_b + st * A_STAGE_B;
        uint32_t bb = sB_b   + st * B_STAGE_B;
        int k0 = st * 32;
        cp_async16_ca(ab + a_dst0, a_src0 + k0);
        cp_async16_ca(ab + a_dst1, a_src1 + k0);
        cp_async16_cg(bb + b_dst0, b_src0 + (size_t)k0 * LDL);
        cp_async16_cg(bb + b_dst1, b_src1 + (size_t)k0 * LDL);
        cp_commit();
    }

    int slot = 0;
    for (int ks = 0; ks < 32; ks++) {
        cp_wait<OUT_STAGES - 2>();
        __syncthreads();

        uint32_t ab = smem_b + slot * A_STAGE_B;
        uint32_t bb = sB_b   + slot * B_STAGE_B;
        #pragma unroll
        for (int kk = 0; kk < 2; kk++) {
            unsigned a[4][4], b[4][2];
            #pragma unroll
            for (int mt = 0; mt < 4; mt++) {
                int chunk = kk * 2 + (lane >> 4);
                uint32_t addr = ab + a_row[mt] * 64 +
                                ((chunk ^ ((a_row[mt] >> 1) & 3)) << 4);
                LDMX4(a[mt][0], a[mt][1], a[mt][2], a[mt][3], addr);
            }
            #pragma unroll
            for (int h = 0; h < 2; h++) {
                int krow = kk * 16 + b_lk;
                int c = wn * 4 + 2 * h + b_lc;
                uint32_t addr = bb + krow * 256 + ((c ^ (krow & 7)) << 4);
                unsigned r0, r1, r2, r3;
                LDMX4T(r0, r1, r2, r3, addr);
                b[2 * h][0] = r0;     b[2 * h][1] = r1;
                b[2 * h + 1][0] = r2; b[2 * h + 1][1] = r3;
            }
            #pragma unroll
            for (int mt = 0; mt < 4; mt++)
                #pragma unroll
                for (int nt = 0; nt < 4; nt++)
                    asm volatile(
                        "mma.sync.aligned.m16n8k16.row.col.f32.bf16.bf16.f32 "
                        "{%0,%1,%2,%3}, {%4,%5,%6,%7}, {%8,%9}, {%0,%1,%2,%3};"
                        : "+f"(acc[mt][nt][0]), "+f"(acc[mt][nt][1]),
                          "+f"(acc[mt][nt][2]), "+f"(acc[mt][nt][3])
                        : "r"(a[mt][0]), "r"(a[mt][1]), "r"(a[mt][2]), "r"(a[mt][3]),
                          "r"(b[nt][0]), "r"(b[nt][1]));
        }

        int nst = ks + OUT_STAGES - 1;
        if (nst < 32) {
            int wslot = nst % OUT_STAGES;
            uint32_t ab2 = smem_b + wslot * A_STAGE_B;
            uint32_t bb2 = sB_b   + wslot * B_STAGE_B;
            int k0 = nst * 32;
            cp_async16_ca(ab2 + a_dst0, a_src0 + k0);
            cp_async16_ca(ab2 + a_dst1, a_src1 + k0);
            cp_async16_cg(bb2 + b_dst0, b_src0 + (size_t)k0 * LDL);
            cp_async16_cg(bb2 + b_dst1, b_src1 + (size_t)k0 * LDL);
            cp_commit();
        }
        slot = (slot + 1 == OUT_STAGES) ? 0 : slot + 1;
    }

    // ---- epilogue: bias, fp32 logits, (max,sumexp) partials ----
    #pragma unroll
    for (int mt = 0; mt < 4; mt++) {
        int row = bm0 + wm * 64 + mt * 16 + g;
        #pragma unroll
        for (int nt = 0; nt < 4; nt++) {
            int col = bn0 + wn * 32 + nt * 8 + 2 * q;
            float b0 = (col < V_SZ)     ? bias[col]     : 0.f;
            float b1 = (col + 1 < V_SZ) ? bias[col + 1] : 0.f;
            acc[mt][nt][0] = (col < V_SZ)     ? acc[mt][nt][0] + b0 : -1e38f;
            acc[mt][nt][1] = (col + 1 < V_SZ) ? acc[mt][nt][1] + b1 : -1e38f;
            acc[mt][nt][2] = (col < V_SZ)     ? acc[mt][nt][2] + b0 : -1e38f;
            acc[mt][nt][3] = (col + 1 < V_SZ) ? acc[mt][nt][3] + b1 : -1e38f;
            float* p0 = g_logits + (size_t)row * LDL + col;
            float* p1 = g_logits + (size_t)(row + 8) * LDL + col;
            p0[0] = acc[mt][nt][0]; p0[1] = acc[mt][nt][1];
            p1[0] = acc[mt][nt][2]; p1[1] = acc[mt][nt][3];
        }
    }

    #pragma unroll
    for (int mt = 0; mt < 4; mt++) {
        #pragma unroll
        for (int half = 0; half < 2; half++) {
            int lr = wm * 64 + mt * 16 + g + 8 * half;
            float mx = -1e38f, sm = 0.f;
            #pragma unroll
            for (int nt = 0; nt < 4; nt++)
                mx = fmaxf(mx, fmaxf(acc[mt][nt][2 * half], acc[mt][nt][2 * half + 1]));
            #pragma unroll
            for (int nt = 0; nt < 4; nt++) {
                float v0 = acc[mt][nt][2 * half], v1 = acc[mt][nt][2 * half + 1];
                if (v0 > -1e37f) sm += expf(v0 - mx);
                if (v1 > -1e37f) sm += expf(v1 - mx);
            }
            #pragma unroll
            for (int o = 1; o <= 2; o <<= 1) {
                float mo = __shfl_xor_sync(0xffffffffu, mx, o);
                float so = __shfl_xor_sync(0xffffffffu, sm, o);
                float mn = fmaxf(mx, mo);
                sm = safe_scale(sm, mx, mn) + safe_scale(so, mo, mn);
                mx = mn;
            }
            if (q == 0) spart[lr][wn] = make_float2(mx, sm);
        }
    }
    __syncthreads();
    if (tid < 128) {
        float mx = -1e38f, sm = 0.f;
        #pragma unroll
        for (int w = 0; w < 4; w++) {
            float2 p = spart[tid][w];
            float mn = fmaxf(mx, p.x);
            sm = safe_scale(sm, mx, mn) + safe_scale(p.y, p.x, mn);
            mx = mn;
        }
        g_part[(size_t)(bm0 + tid) * 400 + blockIdx.y] = make_float2(mx, sm);
    }
}

// ===========================================================================
// K5: log_softmax from partials (R4-exact: one block per row)
// ===========================================================================
__global__ void __launch_bounds__(256) lsm_kernel(float* __restrict__ outp)
{
    __shared__ float sredm[8];
    __shared__ float sreds[8];
    int row = blockIdx.x, tid = threadIdx.x, lane = tid & 31, warp = tid >> 5;

    float m = -1e38f, s = 0.f;
    for (int i = tid; i < NB_T; i += 256) {
        float2 p = g_part[(size_t)row * 400 + i];
        float mn = fmaxf(m, p.x);
        s = safe_scale(s, m, mn) + safe_scale(p.y, p.x, mn);
        m = mn;
    }
    #pragma unroll
    for (int o = 16; o; o >>= 1) {
        float mo = __shfl_xor_sync(0xffffffffu, m, o);
        float so = __shfl_xor_sync(0xffffffffu, s, o);
        float mn = fmaxf(m, mo);
        s = safe_scale(s, m, mn) + safe_scale(so, mo, mn);
        m = mn;
    }
    if (lane == 0) { sredm[warp] = m; sreds[warp] = s; }
    __syncthreads();
    float mall = sredm[0];
    #pragma unroll
    for (int i = 1; i < 8; i++) mall = fmaxf(mall, sredm[i]);
    float tot = 0.f;
    #pragma unroll
    for (int i = 0; i < 8; i++) tot += safe_scale(sreds[i], sredm[i], mall);
    float lse = mall + logf(tot);

    const float* lg = g_logits + (size_t)row * LDL;
    float* op = outp + (size_t)row * V_SZ;
    for (int v = tid * 4; v + 3 < V_SZ; v += 1024) {
        float4 x = *(const float4*)(lg + v);
        op[v]     = x.x - lse;
        op[v + 1] = x.y - lse;
        op[v + 2] = x.z - lse;
        op[v + 3] = x.w - lse;
    }
    if (tid == 0) op[V_SZ - 1] = lg[V_SZ - 1] - lse;   // 50256 tail
}

// ===========================================================================
// host launcher — R4 ordering, attn+convw merged
// ===========================================================================
extern "C" void kernel_launch(void* const* d_in, const int* in_sizes, int n_in,
                              void* d_out, int out_size)
{
    const float* input_emb = (const float*)d_in[0];
    const float* hidden    = (const float*)d_in[1];
    const float* enc       = (const float*)d_in[2];
    const float* attn_W    = (const float*)d_in[3];
    const float* attn_b    = (const float*)d_in[4];
    const float* comb_W    = (const float*)d_in[5];
    const float* comb_b    = (const float*)d_in[6];
    const float* W_ih      = (const float*)d_in[7];
    const float* W_hh      = (const float*)d_in[8];
    const float* b_ih      = (const float*)d_in[9];
    const float* b_hh      = (const float*)d_in[10];
    const float* out_W     = (const float*)d_in[11];
    const float* out_b     = (const float*)d_in[12];

    float* outp = (float*)d_out;
    long long osz = (long long)out_size;
    const long long OV = (long long)B_SZ * V_SZ;
    float* h1_out = (osz >= OV + (long long)B_SZ * H_SZ)
                        ? outp + (size_t)OV : nullptr;
    float* aw_out = (osz >= OV + (long long)B_SZ * H_SZ + (long long)B_SZ * L_SZ)
                        ? outp + (size_t)OV + (size_t)B_SZ * H_SZ : nullptr;

    const int OUT_SMEM = OUT_STAGES * (A_STAGE_B + B_STAGE_B);   // 80KB
    cudaFuncSetAttribute(gemm_out_kernel,
                         cudaFuncAttributeMaxDynamicSharedMemorySize, OUT_SMEM);

    // K0: attn (128 blocks) + convw (25152 blocks) in one launch
    attn_convw_kernel<<<128 + H_SZ * (LDL / 8) / 256, 256>>>(
        input_emb, hidden, enc, attn_W, attn_b, aw_out, out_W);
    // K1: comb + ghh (R4-exact)
    {
        dim3 grid(B_SZ / 64, 16, 4);
        comb_ghh_kernel<<<grid, 256>>>(comb_W, comb_b, hidden, W_hh, b_hh);
    }
    // K2: gih (R4-exact)
    {
        dim3 grid(B_SZ / 64, 3 * H_SZ / 64);
        gemm_gih_kernel<<<grid, 256>>>(W_ih, b_ih);
    }
    // K3: GRU
    gru_kernel<<<(B_SZ * H_SZ) / 256, 256>>>(hidden, h1_out);
    // K4: vocab GEMM
    {
        dim3 grid(B_SZ / 128, NB_T);   // m fastest -> L2 reuse of W tiles
        gemm_out_kernel<<<grid, 256, OUT_SMEM>>>(out_b);
    }
    // K5: log_softmax
    lsm_kernel<<<B_SZ, 256>>>(outp);
}

// round 16
// speedup vs baseline: 1.4461x; 1.2306x over previous
#include <cuda_runtime.h>
#include <cuda_bf16.h>
#include <cuda_fp16.h>
#include <cstdint>

#define B_SZ 512
#define H_SZ 1024
#define L_SZ 64
#define V_SZ 50257
#define LDL  50304   // padded logits / W row stride (128*393)
#define NB_T 393     // 128-wide n-tiles in vocab GEMM

// ---------------- scratch (device globals; no allocation allowed) ----------
__device__ __half g_xinh[B_SZ * 2 * H_SZ];            // fp16 concat input
__device__ __half g_h0h[B_SZ * H_SZ];                 // fp16 h0
__device__ __half g_xh[B_SZ * H_SZ];                  // fp16 comb output
__device__ __half g_combh[2 * H_SZ * H_SZ];           // fp16 comb_W (k,n)
__device__ __half g_wihT[H_SZ * 3 * H_SZ];            // fp16 W_ih^T (k,n)
__device__ __half g_whhT[H_SZ * 3 * H_SZ];            // fp16 W_hh^T (k,n)
__device__ float g_gi[B_SZ * 3 * H_SZ];
__device__ float g_gh[B_SZ * 3 * H_SZ];
__device__ __nv_bfloat16 g_h1b[B_SZ * H_SZ];
__device__ __nv_bfloat16 g_wbf[(size_t)H_SZ * LDL];   // bf16 out_W k-major padded
__device__ float g_logits[(size_t)B_SZ * LDL];
__device__ float2 g_part[B_SZ * 400];

// ---------------- helpers ----------------
__device__ __forceinline__ void cp_async16_cg(uint32_t dst, const void* src) {
    asm volatile("cp.async.cg.shared.global [%0], [%1], 16;" :: "r"(dst), "l"(src));
}
__device__ __forceinline__ void cp_async16_ca(uint32_t dst, const void* src) {
    asm volatile("cp.async.ca.shared.global [%0], [%1], 16;" :: "r"(dst), "l"(src));
}
__device__ __forceinline__ void cp_commit() {
    asm volatile("cp.async.commit_group;");
}
template <int N>
__device__ __forceinline__ void cp_wait() {
    asm volatile("cp.async.wait_group %0;" :: "n"(N));
}
__device__ __forceinline__ uint32_t smem_u32(const void* p) {
    return (uint32_t)__cvta_generic_to_shared(p);
}
#define LDMX4(R0,R1,R2,R3,ADDR) \
    asm volatile("ldmatrix.sync.aligned.m8n8.x4.shared.b16 {%0,%1,%2,%3}, [%4];" \
        : "=r"(R0), "=r"(R1), "=r"(R2), "=r"(R3) : "r"(ADDR))
#define LDMX4T(R0,R1,R2,R3,ADDR) \
    asm volatile("ldmatrix.sync.aligned.m8n8.x4.trans.shared.b16 {%0,%1,%2,%3}, [%4];" \
        : "=r"(R0), "=r"(R1), "=r"(R2), "=r"(R3) : "r"(ADDR))

__device__ __forceinline__ float safe_scale(float s, float m, float mn) {
    return (m > -1e37f) ? s * expf(m - mn) : 0.f;
}

#define MMA_BF16(ACC, A0,A1,A2,A3, B0,B1) \
    asm volatile("mma.sync.aligned.m16n8k16.row.col.f32.bf16.bf16.f32 " \
        "{%0,%1,%2,%3}, {%4,%5,%6,%7}, {%8,%9}, {%0,%1,%2,%3};" \
        : "+f"((ACC)[0]), "+f"((ACC)[1]), "+f"((ACC)[2]), "+f"((ACC)[3]) \
        : "r"(A0), "r"(A1), "r"(A2), "r"(A3), "r"(B0), "r"(B1))
#define MMA_F16(ACC, A0,A1,A2,A3, B0,B1) \
    asm volatile("mma.sync.aligned.m16n8k16.row.col.f32.f16.f16.f32 " \
        "{%0,%1,%2,%3}, {%4,%5,%6,%7}, {%8,%9}, {%0,%1,%2,%3};" \
        : "+f"((ACC)[0]), "+f"((ACC)[1]), "+f"((ACC)[2]), "+f"((ACC)[3]) \
        : "r"(A0), "r"(A1), "r"(A2), "r"(A3), "r"(B0), "r"(B1))

// ===========================================================================
// K0: attn (blocks 0..127, writes fp16 xin/h0) + convw (blocks 128..)
// ===========================================================================
__global__ void __launch_bounds__(256) attn_convw_kernel(
    const float* __restrict__ emb, const float* __restrict__ h0,
    const float* __restrict__ enc, const float* __restrict__ attn_W,
    const float* __restrict__ attn_b, float* __restrict__ aw_out,
    const float* __restrict__ W)
{
    __shared__ float sE[4][H_SZ];
    __shared__ float sH[4][H_SZ];
    __shared__ float sS[4][L_SZ];
    __shared__ float sP[4][4][L_SZ];

    int tid = threadIdx.x;

    if (blockIdx.x >= 128) {
        // ---- convw: out_W fp32 -> g_wbf bf16 padded k-major ----
        size_t id = (size_t)(blockIdx.x - 128) * 256 + tid;
        int k  = (int)(id / (LDL / 8));
        int n8 = (int)(id % (LDL / 8)) * 8;
        const float* wr = W + (size_t)k * V_SZ;
        float f[8];
        if (n8 + 7 < V_SZ) {
            #pragma unroll
            for (int j = 0; j < 8; j++) f[j] = wr[n8 + j];
        } else {
            #pragma unroll
            for (int j = 0; j < 8; j++) f[j] = (n8 + j < V_SZ) ? wr[n8 + j] : 0.f;
        }
        __nv_bfloat162 p0 = __floats2bfloat162_rn(f[0], f[1]);
        __nv_bfloat162 p1 = __floats2bfloat162_rn(f[2], f[3]);
        __nv_bfloat162 p2 = __floats2bfloat162_rn(f[4], f[5]);
        __nv_bfloat162 p3 = __floats2bfloat162_rn(f[6], f[7]);
        uint4 v; v.x = *(unsigned*)&p0; v.y = *(unsigned*)&p1;
        v.z = *(unsigned*)&p2; v.w = *(unsigned*)&p3;
        *(uint4*)&g_wbf[(size_t)k * LDL + n8] = v;
        return;
    }

    // ---- attention ----
    int r0 = blockIdx.x * 4;

    for (int i = tid; i < 4 * H_SZ; i += 256) {
        int r = i >> 10, c = i & 1023;
        sE[r][c] = emb[(size_t)(r0 + r) * H_SZ + c];
        sH[r][c] = h0 [(size_t)(r0 + r) * H_SZ + c];
    }
    __syncthreads();

    {
        int l = tid & 63, gq = tid >> 6;
        float acc[4] = {0.f, 0.f, 0.f, 0.f};
        int kbeg = gq * 512, kend = kbeg + 512;
        for (int k = kbeg; k < kend; k++) {
            float w = attn_W[(size_t)k * L_SZ + l];
            if (k < H_SZ) {
                #pragma unroll
                for (int r = 0; r < 4; r++) acc[r] += sE[r][k] * w;
            } else {
                #pragma unroll
                for (int r = 0; r < 4; r++) acc[r] += sH[r][k - H_SZ] * w;
            }
        }
        #pragma unroll
        for (int r = 0; r < 4; r++) sP[gq][r][l] = acc[r];
    }
    __syncthreads();
    {
        int r = tid >> 6, l = tid & 63;
        sS[r][l] = sP[0][r][l] + sP[1][r][l] + sP[2][r][l] + sP[3][r][l] + attn_b[l];
    }
    __syncthreads();

    int warp = tid >> 5, lane = tid & 31;
    if (warp < 4) {
        int r = warp;
        float v0 = sS[r][lane], v1 = sS[r][lane + 32];
        float m = fmaxf(v0, v1);
        #pragma unroll
        for (int o = 16; o; o >>= 1) m = fmaxf(m, __shfl_xor_sync(0xffffffffu, m, o));
        float e0 = expf(v0 - m), e1 = expf(v1 - m);
        float s = e0 + e1;
        #pragma unroll
        for (int o = 16; o; o >>= 1) s += __shfl_xor_sync(0xffffffffu, s, o);
        float inv = 1.0f / s;
        float w0 = e0 * inv, w1 = e1 * inv;
        sS[r][lane] = w0; sS[r][lane + 32] = w1;
        if (aw_out) {
            aw_out[(size_t)(r0 + r) * L_SZ + lane]      = w0;
            aw_out[(size_t)(r0 + r) * L_SZ + lane + 32] = w1;
        }
    }
    __syncthreads();

    for (int cc = 0; cc < 4; cc++) {
        int h = cc * 256 + tid;
        float a[4] = {0.f, 0.f, 0.f, 0.f};
        for (int l = 0; l < L_SZ; l++) {
            float e = enc[(size_t)l * H_SZ + h];
            #pragma unroll
            for (int r = 0; r < 4; r++) a[r] += sS[r][l] * e;
        }
        #pragma unroll
        for (int r = 0; r < 4; r++) {
            g_xinh[(size_t)(r0 + r) * (2 * H_SZ) + h]        = __float2half(sE[r][h]);
            g_xinh[(size_t)(r0 + r) * (2 * H_SZ) + H_SZ + h] = __float2half(a[r]);
            g_h0h [(size_t)(r0 + r) * H_SZ + h]              = __float2half(sH[r][h]);
        }
    }
}

// ===========================================================================
// K0b: convert mid weights to fp16.
//   blocks [0,1024): comb_W (2048x1024 (k,n)) -> fp16 direct
//   blocks [1024,1792): W_ih ((n,k)) -> g_wihT (k,n)
//   blocks [1792,2560): W_hh -> g_whhT
// ===========================================================================
__global__ void __launch_bounds__(256) convmid_kernel(
    const float* __restrict__ comb_W, const float* __restrict__ W_ih,
    const float* __restrict__ W_hh)
{
    int blk = blockIdx.x, tid = threadIdx.x;
    if (blk < 1024) {
        size_t e8 = ((size_t)blk * 256 + tid) * 8;
        float f[8];
        #pragma unroll
        for (int j = 0; j < 8; j++) f[j] = comb_W[e8 + j];
        __half2 p0 = __floats2half2_rn(f[0], f[1]);
        __half2 p1 = __floats2half2_rn(f[2], f[3]);
        __half2 p2 = __floats2half2_rn(f[4], f[5]);
        __half2 p3 = __floats2half2_rn(f[6], f[7]);
        uint4 v; v.x = *(unsigned*)&p0; v.y = *(unsigned*)&p1;
        v.z = *(unsigned*)&p2; v.w = *(unsigned*)&p3;
        *(uint4*)&g_combh[e8] = v;
        return;
    }
    __shared__ float ts[64][65];
    const float* src = (blk < 1792) ? W_ih : W_hh;
    __half* dst = (blk < 1792) ? g_wihT : g_whhT;
    int t = (blk < 1792) ? blk - 1024 : blk - 1792;   // 0..767
    int bk = (t & 15) * 64;        // k tile
    int bn = (t >> 4) * 64;        // n tile
    #pragma unroll
    for (int i = 0; i < 16; i++) {
        int idx = tid + i * 256;
        int nr = idx >> 6, kc = idx & 63;
        ts[nr][kc] = src[(size_t)(bn + nr) * H_SZ + bk + kc];
    }
    __syncthreads();
    #pragma unroll
    for (int i = 0; i < 8; i++) {
        int idx = tid + i * 256;
        int kr = idx >> 5, np = (idx & 31) * 2;
        __half2 p = __floats2half2_rn(ts[np][kr], ts[np + 1][kr]);
        *(unsigned*)&dst[(size_t)(bk + kr) * (3 * H_SZ) + bn + np] = *(unsigned*)&p;
    }
}

// ===========================================================================
// fp16 mid-GEMM core (structure = measured-262TF/s vocab core).
//   Tile 128m x 128n x 32k, 5-stage cp.async, ldmatrix, m16n8k16.f16.
// ===========================================================================
#define OUT_STAGES 5
#define A_STAGE_B  8192
#define B_STAGE_B  8192

__device__ __forceinline__ void gemm_h16_core(
    char* dynraw,
    const __half* __restrict__ A, int lda,
    const __half* __restrict__ Bkn, int ldb,
    const float* __restrict__ bias,
    float* __restrict__ Cf, __half* __restrict__ Ch, int ldc,
    int K, int relu, int bm0, int bn0)
{
    int tid = threadIdx.x;
    int warp = tid >> 5, lane = tid & 31, g = lane >> 2, q = lane & 3;
    int wm = warp & 1, wn = warp >> 1;

    uint32_t smem_b = smem_u32(dynraw);
    uint32_t sB_b   = smem_b + OUT_STAGES * A_STAGE_B;

    int a_r0 = tid >> 2,  a_c0 = tid & 3;
    int b_k0 = tid >> 4,  b_c0 = tid & 15;
    uint32_t a_dst0 = a_r0 * 64 + ((a_c0 ^ ((a_r0 >> 1) & 3)) << 4);
    uint32_t a_dst1 = (a_r0 + 64) * 64 + ((a_c0 ^ (((a_r0 + 64) >> 1) & 3)) << 4);
    uint32_t b_dst0 = b_k0 * 256 + ((b_c0 ^ (b_k0 & 7)) << 4);
    uint32_t b_dst1 = (b_k0 + 16) * 256 + ((b_c0 ^ ((b_k0 + 16) & 7)) << 4);
    const __half* a_src0 = A + (size_t)(bm0 + a_r0) * lda + a_c0 * 8;
    const __half* a_src1 = A + (size_t)(bm0 + a_r0 + 64) * lda + a_c0 * 8;
    const __half* b_src0 = Bkn + (size_t)b_k0 * ldb + bn0 + b_c0 * 8;
    const __half* b_src1 = Bkn + (size_t)(b_k0 + 16) * ldb + bn0 + b_c0 * 8;

    int a_row[4];
    #pragma unroll
    for (int mt = 0; mt < 4; mt++) a_row[mt] = wm * 64 + mt * 16 + (lane & 15);
    int b_lk = lane & 15, b_lc = lane >> 4;

    float acc[4][4][4];
    #pragma unroll
    for (int i = 0; i < 4; i++)
        #pragma unroll
        for (int j = 0; j < 4; j++)
            #pragma unroll
            for (int t = 0; t < 4; t++) acc[i][j][t] = 0.f;

    const int NSTG = K / 32;
    #pragma unroll
    for (int st = 0; st < OUT_STAGES - 1; st++) {
        uint32_t ab = smem_b + st * A_STAGE_B;
        uint32_t bb = sB_b   + st * B_STAGE_B;
        int k0 = st * 32;
        cp_async16_ca(ab + a_dst0, a_src0 + k0);
        cp_async16_ca(ab + a_dst1, a_src1 + k0);
        cp_async16_cg(bb + b_dst0, b_src0 + (size_t)k0 * ldb);
        cp_async16_cg(bb + b_dst1, b_src1 + (size_t)k0 * ldb);
        cp_commit();
    }

    int slot = 0;
    for (int ks = 0; ks < NSTG; ks++) {
        cp_wait<OUT_STAGES - 2>();
        __syncthreads();

        uint32_t ab = smem_b + slot * A_STAGE_B;
        uint32_t bb = sB_b   + slot * B_STAGE_B;
        #pragma unroll
        for (int kk = 0; kk < 2; kk++) {
            unsigned a[4][4], b[4][2];
            #pragma unroll
            for (int mt = 0; mt < 4; mt++) {
                int chunk = kk * 2 + (lane >> 4);
                uint32_t addr = ab + a_row[mt] * 64 +
                                ((chunk ^ ((a_row[mt] >> 1) & 3)) << 4);
                LDMX4(a[mt][0], a[mt][1], a[mt][2], a[mt][3], addr);
            }
            #pragma unroll
            for (int h = 0; h < 2; h++) {
                int krow = kk * 16 + b_lk;
                int c = wn * 4 + 2 * h + b_lc;
                uint32_t addr = bb + krow * 256 + ((c ^ (krow & 7)) << 4);
                unsigned r0, r1, r2, r3;
                LDMX4T(r0, r1, r2, r3, addr);
                b[2 * h][0] = r0;     b[2 * h][1] = r1;
                b[2 * h + 1][0] = r2; b[2 * h + 1][1] = r3;
            }
            #pragma unroll
            for (int mt = 0; mt < 4; mt++)
                #pragma unroll
                for (int nt = 0; nt < 4; nt++)
                    MMA_F16(acc[mt][nt], a[mt][0], a[mt][1], a[mt][2], a[mt][3],
                            b[nt][0], b[nt][1]);
        }

        int nst = ks + OUT_STAGES - 1;
        if (nst < NSTG) {
            int wslot = nst % OUT_STAGES;
            uint32_t ab2 = smem_b + wslot * A_STAGE_B;
            uint32_t bb2 = sB_b   + wslot * B_STAGE_B;
            int k0 = nst * 32;
            cp_async16_ca(ab2 + a_dst0, a_src0 + k0);
            cp_async16_ca(ab2 + a_dst1, a_src1 + k0);
            cp_async16_cg(bb2 + b_dst0, b_src0 + (size_t)k0 * ldb);
            cp_async16_cg(bb2 + b_dst1, b_src1 + (size_t)k0 * ldb);
            cp_commit();
        }
        slot = (slot + 1 == OUT_STAGES) ? 0 : slot + 1;
    }

    // epilogue
    #pragma unroll
    for (int mt = 0; mt < 4; mt++) {
        int row = bm0 + wm * 64 + mt * 16 + g;
        #pragma unroll
        for (int nt = 0; nt < 4; nt++) {
            int col = bn0 + wn * 32 + nt * 8 + 2 * q;
            float b0 = bias[col], b1 = bias[col + 1];
            float v0 = acc[mt][nt][0] + b0, v1 = acc[mt][nt][1] + b1;
            float v2 = acc[mt][nt][2] + b0, v3 = acc[mt][nt][3] + b1;
            if (relu) {
                v0 = fmaxf(v0, 0.f); v1 = fmaxf(v1, 0.f);
                v2 = fmaxf(v2, 0.f); v3 = fmaxf(v3, 0.f);
            }
            if (Ch) {
                __half2 p0 = __floats2half2_rn(v0, v1);
                __half2 p1 = __floats2half2_rn(v2, v3);
                *(unsigned*)&Ch[(size_t)row * ldc + col]       = *(unsigned*)&p0;
                *(unsigned*)&Ch[(size_t)(row + 8) * ldc + col] = *(unsigned*)&p1;
            } else {
                Cf[(size_t)row * ldc + col]           = v0;
                Cf[(size_t)row * ldc + col + 1]       = v1;
                Cf[(size_t)(row + 8) * ldc + col]     = v2;
                Cf[(size_t)(row + 8) * ldc + col + 1] = v3;
            }
        }
    }
}

// K2: comb (blocks 0..31) + ghh (blocks 32..127)
__global__ void __launch_bounds__(256, 2) comb_ghh_kernel(
    const float* __restrict__ comb_b, const float* __restrict__ b_hh)
{
    extern __shared__ char dynraw[];
    int bid = blockIdx.x;
    if (bid < 32) {
        gemm_h16_core(dynraw, g_xinh, 2 * H_SZ, g_combh, H_SZ,
                      comb_b, nullptr, g_xh, H_SZ, 2 * H_SZ, 1,
                      (bid & 3) * 128, (bid >> 2) * 128);
    } else {
        int t = bid - 32;   // 0..95
        gemm_h16_core(dynraw, g_h0h, H_SZ, g_whhT, 3 * H_SZ,
                      b_hh, g_gh, nullptr, 3 * H_SZ, H_SZ, 0,
                      (t & 3) * 128, (t >> 2) * 128);
    }
}
// K3: gih
__global__ void __launch_bounds__(256, 2) gih_kernel(const float* __restrict__ b_ih)
{
    extern __shared__ char dynraw[];
    int t = blockIdx.x;   // 0..95
    gemm_h16_core(dynraw, g_xh, H_SZ, g_wihT, 3 * H_SZ,
                  b_ih, g_gi, nullptr, 3 * H_SZ, H_SZ, 0,
                  (t & 3) * 128, (t >> 2) * 128);
}

// ===========================================================================
// K4: GRU elementwise (R15-exact)
// ===========================================================================
__global__ void __launch_bounds__(256) gru_kernel(
    const float* __restrict__ h0, float* __restrict__ h1_extra)
{
    int idx = blockIdx.x * 256 + threadIdx.x;
    if (idx >= B_SZ * H_SZ) return;
    int row = idx >> 10, j = idx & 1023;
    const float* gi = g_gi + (size_t)row * 3 * H_SZ;
    const float* gh = g_gh + (size_t)row * 3 * H_SZ;
    float rg = 1.f / (1.f + expf(-(gi[j] + gh[j])));
    float zg = 1.f / (1.f + expf(-(gi[H_SZ + j] + gh[H_SZ + j])));
    float ng = tanhf(gi[2 * H_SZ + j] + rg * gh[2 * H_SZ + j]);
    float h0v = h0[idx];
    float h1 = (1.f - zg) * ng + zg * h0v;
    g_h1b[idx] = __float2bfloat16(h1);
    if (h1_extra) h1_extra[idx] = h1;
}

// ===========================================================================
// K5: vocab GEMM (R15-exact), fp32 logits + (max,sumexp) partials.
// ===========================================================================
__global__ void __launch_bounds__(256, 2) gemm_out_kernel(
    const float* __restrict__ bias)
{
    extern __shared__ __nv_bfloat16 dynsmem[];
    __shared__ float2 spart[128][4];

    const int K = 1024;
    int tid = threadIdx.x;
    int warp = tid >> 5, lane = tid & 31, g = lane >> 2, q = lane & 3;
    int wm = warp & 1, wn = warp >> 1;
    int bm0 = blockIdx.x * 128, bn0 = blockIdx.y * 128;

    uint32_t smem_b = smem_u32(dynsmem);
    uint32_t sB_b   = smem_b + OUT_STAGES * A_STAGE_B;

    int a_r0 = tid >> 2,  a_c0 = tid & 3;
    int b_k0 = tid >> 4,  b_c0 = tid & 15;
    uint32_t a_dst0 = a_r0 * 64 + ((a_c0 ^ ((a_r0 >> 1) & 3)) << 4);
    uint32_t a_dst1 = (a_r0 + 64) * 64 + ((a_c0 ^ (((a_r0 + 64) >> 1) & 3)) << 4);
    uint32_t b_dst0 = b_k0 * 256 + ((b_c0 ^ (b_k0 & 7)) << 4);
    uint32_t b_dst1 = (b_k0 + 16) * 256 + ((b_c0 ^ ((b_k0 + 16) & 7)) << 4);
    const __nv_bfloat16* a_src0 = g_h1b + (size_t)(bm0 + a_r0) * K + a_c0 * 8;
    const __nv_bfloat16* a_src1 = g_h1b + (size_t)(bm0 + a_r0 + 64) * K + a_c0 * 8;
    const __nv_bfloat16* b_src0 = g_wbf + (size_t)b_k0 * LDL + bn0 + b_c0 * 8;
    const __nv_bfloat16* b_src1 = g_wbf + (size_t)(b_k0 + 16) * LDL + bn0 + b_c0 * 8;

    int a_row[4];
    #pragma unroll
    for (int mt = 0; mt < 4; mt++) a_row[mt] = wm * 64 + mt * 16 + (lane & 15);
    int b_lk = lane & 15, b_lc = lane >> 4;

    float acc[4][4][4];
    #pragma unroll
    for (int i = 0; i < 4; i++)
        #pragma unroll
        for (int j = 0; j < 4; j++)
            #pragma unroll
            for (int t = 0; t < 4; t++) acc[i][j][t] = 0.f;

    #pragma unroll
    for (int st = 0; st < OUT_STAGES - 1; st++) {
        uint32_t ab = smem_b + st * A_STAGE_B;
        uint32_t bb = sB_b   + st * B_STAGE_B;
        int k0 = st * 32;
        cp_async16_ca(ab + a_dst0, a_src0 + k0);
        cp_async16_ca(ab + a_dst1, a_src1 + k0);
        cp_async16_cg(bb + b_dst0, b_src0 + (size_t)k0 * LDL);
        cp_async16_cg(bb + b_dst1, b_src1 + (size_t)k0 * LDL);
        cp_commit();
    }

    int slot = 0;
    for (int ks = 0; ks < 32; ks++) {
        cp_wait<OUT_STAGES - 2>();
        __syncthreads();

        uint32_t ab = smem_b + slot * A_STAGE_B;
        uint32_t bb = sB_b   + slot * B_STAGE_B;
        #pragma unroll
        for (int kk = 0; kk < 2; kk++) {
            unsigned a[4][4], b[4][2];
            #pragma unroll
            for (int mt = 0; mt < 4; mt++) {
                int chunk = kk * 2 + (lane >> 4);
                uint32_t addr = ab + a_row[mt] * 64 +
                                ((chunk ^ ((a_row[mt] >> 1) & 3)) << 4);
                LDMX4(a[mt][0], a[mt][1], a[mt][2], a[mt][3], addr);
            }
            #pragma unroll
            for (int h = 0; h < 2; h++) {
                int krow = kk * 16 + b_lk;
                int c = wn * 4 + 2 * h + b_lc;
                uint32_t addr = bb + krow * 256 + ((c ^ (krow & 7)) << 4);
                unsigned r0, r1, r2, r3;
                LDMX4T(r0, r1, r2, r3, addr);
                b[2 * h][0] = r0;     b[2 * h][1] = r1;
                b[2 * h + 1][0] = r2; b[2 * h + 1][1] = r3;
            }
            #pragma unroll
            for (int mt = 0; mt < 4; mt++)
                #pragma unroll
                for (int nt = 0; nt < 4; nt++)
                    MMA_BF16(acc[mt][nt], a[mt][0], a[mt][1], a[mt][2], a[mt][3],
                             b[nt][0], b[nt][1]);
        }

        int nst = ks + OUT_STAGES - 1;
        if (nst < 32) {
            int wslot = nst % OUT_STAGES;
            uint32_t ab2 = smem_b + wslot * A_STAGE_B;
            uint32_t bb2 = sB_b   + wslot * B_STAGE_B;
            int k0 = nst * 32;
            cp_async16_ca(ab2 + a_dst0, a_src0 + k0);
            cp_async16_ca(ab2 + a_dst1, a_src1 + k0);
            cp_async16_cg(bb2 + b_dst0, b_src0 + (size_t)k0 * LDL);
            cp_async16_cg(bb2 + b_dst1, b_src1 + (size_t)k0 * LDL);
            cp_commit();
        }
        slot = (slot + 1 == OUT_STAGES) ? 0 : slot + 1;
    }

    // ---- epilogue: bias, fp32 logits, (max,sumexp) partials ----
    #pragma unroll
    for (int mt = 0; mt < 4; mt++) {
        int row = bm0 + wm * 64 + mt * 16 + g;
        #pragma unroll
        for (int nt = 0; nt < 4; nt++) {
            int col = bn0 + wn * 32 + nt * 8 + 2 * q;
            float b0 = (col < V_SZ)     ? bias[col]     : 0.f;
            float b1 = (col + 1 < V_SZ) ? bias[col + 1] : 0.f;
            acc[mt][nt][0] = (col < V_SZ)     ? acc[mt][nt][0] + b0 : -1e38f;
            acc[mt][nt][1] = (col + 1 < V_SZ) ? acc[mt][nt][1] + b1 : -1e38f;
            acc[mt][nt][2] = (col < V_SZ)     ? acc[mt][nt][2] + b0 : -1e38f;
            acc[mt][nt][3] = (col + 1 < V_SZ) ? acc[mt][nt][3] + b1 : -1e38f;
            float* p0 = g_logits + (size_t)row * LDL + col;
            float* p1 = g_logits + (size_t)(row + 8) * LDL + col;
            p0[0] = acc[mt][nt][0]; p0[1] = acc[mt][nt][1];
            p1[0] = acc[mt][nt][2]; p1[1] = acc[mt][nt][3];
        }
    }

    #pragma unroll
    for (int mt = 0; mt < 4; mt++) {
        #pragma unroll
        for (int half = 0; half < 2; half++) {
            int lr = wm * 64 + mt * 16 + g + 8 * half;
            float mx = -1e38f, sm = 0.f;
            #pragma unroll
            for (int nt = 0; nt < 4; nt++)
                mx = fmaxf(mx, fmaxf(acc[mt][nt][2 * half], acc[mt][nt][2 * half + 1]));
            #pragma unroll
            for (int nt = 0; nt < 4; nt++) {
                float v0 = acc[mt][nt][2 * half], v1 = acc[mt][nt][2 * half + 1];
                if (v0 > -1e37f) sm += expf(v0 - mx);
                if (v1 > -1e37f) sm += expf(v1 - mx);
            }
            #pragma unroll
            for (int o = 1; o <= 2; o <<= 1) {
                float mo = __shfl_xor_sync(0xffffffffu, mx, o);
                float so = __shfl_xor_sync(0xffffffffu, sm, o);
                float mn = fmaxf(mx, mo);
                sm = safe_scale(sm, mx, mn) + safe_scale(so, mo, mn);
                mx = mn;
            }
            if (q == 0) spart[lr][wn] = make_float2(mx, sm);
        }
    }
    __syncthreads();
    if (tid < 128) {
        float mx = -1e38f, sm = 0.f;
        #pragma unroll
        for (int w = 0; w < 4; w++) {
            float2 p = spart[tid][w];
            float mn = fmaxf(mx, p.x);
            sm = safe_scale(sm, mx, mn) + safe_scale(p.y, p.x, mn);
            mx = mn;
        }
        g_part[(size_t)(bm0 + tid) * 400 + blockIdx.y] = make_float2(mx, sm);
    }
}

// ===========================================================================
// K6: log_softmax from partials (R15-exact)
// ===========================================================================
__global__ void __launch_bounds__(256) lsm_kernel(float* __restrict__ outp)
{
    __shared__ float sredm[8];
    __shared__ float sreds[8];
    int row = blockIdx.x, tid = threadIdx.x, lane = tid & 31, warp = tid >> 5;

    float m = -1e38f, s = 0.f;
    for (int i = tid; i < NB_T; i += 256) {
        float2 p = g_part[(size_t)row * 400 + i];
        float mn = fmaxf(m, p.x);
        s = safe_scale(s, m, mn) + safe_scale(p.y, p.x, mn);
        m = mn;
    }
    #pragma unroll
    for (int o = 16; o; o >>= 1) {
        float mo = __shfl_xor_sync(0xffffffffu, m, o);
        float so = __shfl_xor_sync(0xffffffffu, s, o);
        float mn = fmaxf(m, mo);
        s = safe_scale(s, m, mn) + safe_scale(so, mo, mn);
        m = mn;
    }
    if (lane == 0) { sredm[warp] = m; sreds[warp] = s; }
    __syncthreads();
    float mall = sredm[0];
    #pragma unroll
    for (int i = 1; i < 8; i++) mall = fmaxf(mall, sredm[i]);
    float tot = 0.f;
    #pragma unroll
    for (int i = 0; i < 8; i++) tot += safe_scale(sreds[i], sredm[i], mall);
    float lse = mall + logf(tot);

    const float* lg = g_logits + (size_t)row * LDL;
    float* op = outp + (size_t)row * V_SZ;
    for (int v = tid * 4; v + 3 < V_SZ; v += 1024) {
        float4 x = *(const float4*)(lg + v);
        op[v]     = x.x - lse;
        op[v + 1] = x.y - lse;
        op[v + 2] = x.z - lse;
        op[v + 3] = x.w - lse;
    }
    if (tid == 0) op[V_SZ - 1] = lg[V_SZ - 1] - lse;   // 50256 tail
}

// ===========================================================================
// host launcher
// ===========================================================================
extern "C" void kernel_launch(void* const* d_in, const int* in_sizes, int n_in,
                              void* d_out, int out_size)
{
    const float* input_emb = (const float*)d_in[0];
    const float* hidden    = (const float*)d_in[1];
    const float* enc       = (const float*)d_in[2];
    const float* attn_W    = (const float*)d_in[3];
    const float* attn_b    = (const float*)d_in[4];
    const float* comb_W    = (const float*)d_in[5];
    const float* comb_b    = (const float*)d_in[6];
    const float* W_ih      = (const float*)d_in[7];
    const float* W_hh      = (const float*)d_in[8];
    const float* b_ih      = (const float*)d_in[9];
    const float* b_hh      = (const float*)d_in[10];
    const float* out_W     = (const float*)d_in[11];
    const float* out_b     = (const float*)d_in[12];

    float* outp = (float*)d_out;
    long long osz = (long long)out_size;
    const long long OV = (long long)B_SZ * V_SZ;
    float* h1_out = (osz >= OV + (long long)B_SZ * H_SZ)
                        ? outp + (size_t)OV : nullptr;
    float* aw_out = (osz >= OV + (long long)B_SZ * H_SZ + (long long)B_SZ * L_SZ)
                        ? outp + (size_t)OV + (size_t)B_SZ * H_SZ : nullptr;

    const int OUT_SMEM = OUT_STAGES * (A_STAGE_B + B_STAGE_B);   // 80KB
    cudaFuncSetAttribute(gemm_out_kernel,
                         cudaFuncAttributeMaxDynamicSharedMemorySize, OUT_SMEM);
    cudaFuncSetAttribute(comb_ghh_kernel,
                         cudaFuncAttributeMaxDynamicSharedMemorySize, OUT_SMEM);
    cudaFuncSetAttribute(gih_kernel,
                         cudaFuncAttributeMaxDynamicSharedMemorySize, OUT_SMEM);

    // K0: attn (128 blocks) + convw (25152 blocks)
    attn_convw_kernel<<<128 + H_SZ * (LDL / 8) / 256, 256>>>(
        input_emb, hidden, enc, attn_W, attn_b, aw_out, out_W);
    // K0b: mid weights -> fp16
    convmid_kernel<<<2560, 256>>>(comb_W, W_ih, W_hh);
    // K1: comb (32) + ghh (96) fp16 tensor core
    comb_ghh_kernel<<<128, 256, OUT_SMEM>>>(comb_b, b_hh);
    // K2: gih (96)
    gih_kernel<<<96, 256, OUT_SMEM>>>(b_ih);
    // K3: GRU
    gru_kernel<<<(B_SZ * H_SZ) / 256, 256>>>(hidden, h1_out);
    // K4: vocab GEMM
    {
        dim3 grid(B_SZ / 128, NB_T);   // m fastest -> L2 reuse of W tiles
        gemm_out_kernel<<<grid, 256, OUT_SMEM>>>(out_b);
    }
    // K5: log_softmax
    lsm_kernel<<<B_SZ, 256>>>(outp);
}